// round 2
// baseline (speedup 1.0000x reference)
#include <cuda_runtime.h>

#define MAXN 50000
#define MAXE 800000
#define DIM 128

// ---------------- scratch (allocation-free, 16B aligned) ----------------
__device__ float4 g_h1[MAXN * 32];    // layer buffers (reused across stages)
__device__ float4 g_h2[MAXN * 32];
__device__ float4 g_acc[MAXN * 32];   // scatter accumulator (reused 3x)
__device__ float g_as[MAXN * 2];
__device__ float g_ad[MAXN * 2];
__device__ float g_den[MAXN * 2];
__device__ float g_cnt[MAXN];
__device__ int g_src[MAXE];
__device__ int g_dst[MAXE];
__device__ int g_is64;

// ---------------- vector reduction helper ----------------
__device__ __forceinline__ void red_add_v4(float4* p, float4 v) {
    asm volatile("red.global.add.v4.f32 [%0], {%1, %2, %3, %4};"
                 :: "l"(p), "f"(v.x), "f"(v.y), "f"(v.z), "f"(v.w) : "memory");
}

// ---------------- dtype sniff: int64 indices have all-zero hi words ----------------
__global__ void detect_kernel(const unsigned int* __restrict__ raw, int E) {
    if (threadIdx.x != 0 || blockIdx.x != 0) return;
    int step = E / 64; if (step < 1) step = 1;
    int allz = 1;
    for (int k = 0; k < 64; k++) {
        long long j = 2LL * (long long)k * step + 1;   // odd word, < 2*E, safe both layouts
        if (j >= 2LL * E) break;
        if (raw[j] != 0u) { allz = 0; break; }
    }
    g_is64 = allz;
}

// ---------------- normalize edge indices to int32 ----------------
__global__ void convert_idx_kernel(const void* __restrict__ raw, int* __restrict__ s,
                                   int* __restrict__ d, int E) {
    int i = blockIdx.x * blockDim.x + threadIdx.x;
    if (i >= E) return;
    if (g_is64) {
        const long long* p = (const long long*)raw;
        s[i] = (int)p[i];
        d[i] = (int)p[E + i];
    } else {
        const int* p = (const int*)raw;
        s[i] = p[i];
        d[i] = p[E + i];
    }
}

// ---------------- GEMM: H[n,128] = X[n,128] @ W[128,128]^T ----------------
// Tile: 64 rows x 128 cols, K=128 in one shot. 256 threads, 4x8 micro-tile.
__global__ void gemm_kernel(const float* __restrict__ X, const float* __restrict__ W,
                            float* __restrict__ H, int nrows) {
    extern __shared__ float sm[];
    float* xs = sm;               // [64][129]
    float* ws = sm + 64 * 129;    // [128][132]  (ws[k][o] = W[o][k])
    int tid = threadIdx.x;
    int row0 = blockIdx.x * 64;

    #pragma unroll
    for (int i = 0; i < 32; i++) {
        int idx = tid + i * 256;
        int r = idx >> 7, k = idx & 127;
        float v = 0.f;
        if (row0 + r < nrows) v = X[(long long)(row0 + r) * DIM + k];
        xs[r * 129 + k] = v;
    }
    #pragma unroll
    for (int i = 0; i < 64; i++) {
        int idx = tid + i * 256;
        int o = idx >> 7, k = idx & 127;
        ws[k * 132 + o] = W[idx];
    }
    __syncthreads();

    int tx = tid & 15, ty = tid >> 4;
    float acc[4][8];
    #pragma unroll
    for (int i = 0; i < 4; i++)
        #pragma unroll
        for (int j = 0; j < 8; j++) acc[i][j] = 0.f;

    #pragma unroll 8
    for (int k = 0; k < 128; k++) {
        float aa[4];
        #pragma unroll
        for (int i = 0; i < 4; i++) aa[i] = xs[(ty * 4 + i) * 129 + k];
        float4 b0 = *(const float4*)&ws[k * 132 + tx * 4];
        float4 b1 = *(const float4*)&ws[k * 132 + 64 + tx * 4];
        float bb[8] = {b0.x, b0.y, b0.z, b0.w, b1.x, b1.y, b1.z, b1.w};
        #pragma unroll
        for (int i = 0; i < 4; i++)
            #pragma unroll
            for (int j = 0; j < 8; j++) acc[i][j] += aa[i] * bb[j];
    }

    #pragma unroll
    for (int i = 0; i < 4; i++) {
        int r = row0 + ty * 4 + i;
        if (r < nrows) {
            float4 v0 = {acc[i][0], acc[i][1], acc[i][2], acc[i][3]};
            float4 v1 = {acc[i][4], acc[i][5], acc[i][6], acc[i][7]};
            *(float4*)&H[(long long)r * DIM + tx * 4] = v0;
            *(float4*)&H[(long long)r * DIM + 64 + tx * 4] = v1;
        }
    }
}

// ---------------- per-node attention logits ----------------
template <int HEADS>
__global__ void alpha_kernel(const float4* __restrict__ h, const float* __restrict__ a_src,
                             const float* __restrict__ a_dst, float* __restrict__ os,
                             float* __restrict__ od, int nrows) {
    int g = blockIdx.x * blockDim.x + threadIdx.x;
    int n = g >> 5, lane = g & 31;
    if (n >= nrows) return;
    float4 hv = h[n * 32 + lane];
    float4 av = ((const float4*)a_src)[lane];  // HEADS*C == 128, layout matches h
    float4 bv = ((const float4*)a_dst)[lane];
    float s = hv.x * av.x + hv.y * av.y + hv.z * av.z + hv.w * av.w;
    float t = hv.x * bv.x + hv.y * bv.y + hv.z * bv.z + hv.w * bv.w;
    #pragma unroll
    for (int off = (HEADS == 2 ? 8 : 16); off >= 1; off >>= 1) {
        s += __shfl_xor_sync(0xffffffff, s, off);
        t += __shfl_xor_sync(0xffffffff, t, off);
    }
    int grp = (HEADS == 2) ? 15 : 31;
    if ((lane & grp) == 0) {
        int head = (HEADS == 2) ? (lane >> 4) : 0;
        os[n * HEADS + head] = s;
        od[n * HEADS + head] = t;
    }
}

// ---------------- fused GAT edge pass: acc[d] += w*h[s], den[d] += w ----------------
template <int HEADS>
__global__ void edge_kernel(const int* __restrict__ src, const int* __restrict__ dst,
                            const float4* __restrict__ h, const float* __restrict__ as_,
                            const float* __restrict__ ad_, float4* __restrict__ acc,
                            float* __restrict__ den, int E, int Ntot) {
    int warp = (blockIdx.x * blockDim.x + threadIdx.x) >> 5;
    int lane = threadIdx.x & 31;
    if (warp >= E + Ntot) return;
    int s, d;
    if (warp < E) { s = src[warp]; d = dst[warp]; }
    else          { s = d = warp - E; }
    int head = (HEADS == 2) ? (lane >> 4) : 0;
    float a = as_[s * HEADS + head] + ad_[d * HEADS + head];
    float e = (a > 0.f) ? a : 0.2f * a;   // leaky_relu(0.2)
    float w = __expf(e);                  // shift-free softmax: bounded logits
    if ((lane & (HEADS == 2 ? 15 : 31)) == 0) atomicAdd(&den[d * HEADS + head], w);
    float4 hv = h[s * 32 + lane];
    float4 v = {w * hv.x, w * hv.y, w * hv.z, w * hv.w};
    red_add_v4(acc + d * 32 + lane, v);
}

// ---------------- node epilogue: out = (acc/den + bias) [relu?] ----------------
template <int HEADS, bool RELU>
__global__ void node_kernel(const float4* __restrict__ acc, const float* __restrict__ den,
                            const float* __restrict__ bias, float4* __restrict__ out, int nrows) {
    int g = blockIdx.x * blockDim.x + threadIdx.x;
    int n = g >> 5, lane = g & 31;
    if (n >= nrows) return;
    int head = (HEADS == 2) ? (lane >> 4) : 0;
    float inv = 1.f / den[n * HEADS + head];
    float4 v = acc[n * 32 + lane];
    float4 b = ((const float4*)bias)[lane];
    float4 r;
    r.x = v.x * inv + b.x; r.y = v.y * inv + b.y;
    r.z = v.z * inv + b.z; r.w = v.w * inv + b.w;
    if (RELU) {
        r.x = fmaxf(r.x, 0.f); r.y = fmaxf(r.y, 0.f);
        r.z = fmaxf(r.z, 0.f); r.w = fmaxf(r.w, 0.f);
    }
    out[n * 32 + lane] = r;
}

// ---------------- mean-conv edge pass (raw edges, no self loops) ----------------
__global__ void mean_edge_kernel(const int* __restrict__ src, const int* __restrict__ dst,
                                 const float4* __restrict__ h, float4* __restrict__ acc,
                                 float* __restrict__ cnt, int E) {
    int warp = (blockIdx.x * blockDim.x + threadIdx.x) >> 5;
    int lane = threadIdx.x & 31;
    if (warp >= E) return;
    int s = src[warp], d = dst[warp];
    if (lane == 0) atomicAdd(&cnt[d], 1.f);
    red_add_v4(acc + d * 32 + lane, h[s * 32 + lane]);
}

// ---------------- final: out = relu(acc/cnt (or 0) + x) ----------------
__global__ void final_kernel(const float4* __restrict__ acc, const float* __restrict__ cnt,
                             const float4* __restrict__ x, float4* __restrict__ out, int nrows) {
    int g = blockIdx.x * blockDim.x + threadIdx.x;
    int n = g >> 5, lane = g & 31;
    if (n >= nrows) return;
    float c = cnt[n];
    float inv = (c > 0.f) ? (1.f / c) : 0.f;
    float4 v = acc[n * 32 + lane];
    float4 xv = x[n * 32 + lane];
    float4 r;
    r.x = fmaxf(v.x * inv + xv.x, 0.f);
    r.y = fmaxf(v.y * inv + xv.y, 0.f);
    r.z = fmaxf(v.z * inv + xv.z, 0.f);
    r.w = fmaxf(v.w * inv + xv.w, 0.f);
    out[n * 32 + lane] = r;
}

// ---------------- launch ----------------
extern "C" void kernel_launch(void* const* d_in, const int* in_sizes, int n_in,
                              void* d_out, int out_size) {
    const float* x    = (const float*)d_in[0];
    const void*  ei   = d_in[1];
    const float* W1   = (const float*)d_in[2];
    const float* asv1 = (const float*)d_in[3];
    const float* adv1 = (const float*)d_in[4];
    const float* b1   = (const float*)d_in[5];
    const float* W2   = (const float*)d_in[6];
    const float* asv2 = (const float*)d_in[7];
    const float* adv2 = (const float*)d_in[8];
    const float* b2   = (const float*)d_in[9];
    float* out = (float*)d_out;

    int n = in_sizes[0] / DIM;
    int E = in_sizes[1] / 2;

    float4 *h1, *h2, *acc;
    float *as_, *ad_, *den, *cnt;
    int *srci, *dsti;
    cudaGetSymbolAddress((void**)&h1,   g_h1);
    cudaGetSymbolAddress((void**)&h2,   g_h2);
    cudaGetSymbolAddress((void**)&acc,  g_acc);
    cudaGetSymbolAddress((void**)&as_,  g_as);
    cudaGetSymbolAddress((void**)&ad_,  g_ad);
    cudaGetSymbolAddress((void**)&den,  g_den);
    cudaGetSymbolAddress((void**)&cnt,  g_cnt);
    cudaGetSymbolAddress((void**)&srci, g_src);
    cudaGetSymbolAddress((void**)&dsti, g_dst);

    const int gemm_smem = (64 * 129 + 128 * 132) * 4;
    cudaFuncSetAttribute(gemm_kernel, cudaFuncAttributeMaxDynamicSharedMemorySize, gemm_smem);

    int gemm_blocks  = (n + 63) / 64;
    int nwarp_blocks = (n * 32 + 255) / 256;
    int edge_blocks  = (E + n + 7) / 8;   // (E+n) warps, 8 warps/block
    int medge_blocks = (E + 7) / 8;

    // ---- normalize edge indices (handles int32 or int64 input) ----
    detect_kernel<<<1, 32>>>((const unsigned int*)ei, E);
    convert_idx_kernel<<<(E + 255) / 256, 256>>>(ei, srci, dsti, E);

    // ---- GAT layer 1 (heads=2, ch=64) ----
    cudaMemsetAsync(acc, 0, (size_t)n * DIM * sizeof(float), 0);
    cudaMemsetAsync(den, 0, (size_t)n * 2 * sizeof(float), 0);
    gemm_kernel<<<gemm_blocks, 256, gemm_smem>>>(x, W1, (float*)h1, n);
    alpha_kernel<2><<<nwarp_blocks, 256>>>(h1, asv1, adv1, as_, ad_, n);
    edge_kernel<2><<<edge_blocks, 256>>>(srci, dsti, h1, as_, ad_, acc, den, E, n);
    node_kernel<2, true><<<nwarp_blocks, 256>>>(acc, den, b1, h1, n);

    // ---- GAT layer 2 (heads=1, ch=128) ----
    cudaMemsetAsync(acc, 0, (size_t)n * DIM * sizeof(float), 0);
    cudaMemsetAsync(den, 0, (size_t)n * sizeof(float), 0);
    gemm_kernel<<<gemm_blocks, 256, gemm_smem>>>((const float*)h1, W2, (float*)h2, n);
    alpha_kernel<1><<<nwarp_blocks, 256>>>(h2, asv2, adv2, as_, ad_, n);
    edge_kernel<1><<<edge_blocks, 256>>>(srci, dsti, h2, as_, ad_, acc, den, E, n);
    node_kernel<1, false><<<nwarp_blocks, 256>>>(acc, den, b2, h1, n);

    // ---- mean conv + residual + relu ----
    cudaMemsetAsync(acc, 0, (size_t)n * DIM * sizeof(float), 0);
    cudaMemsetAsync(cnt, 0, (size_t)n * sizeof(float), 0);
    mean_edge_kernel<<<medge_blocks, 256>>>(srci, dsti, h1, acc, cnt, E);
    final_kernel<<<nwarp_blocks, 256>>>(acc, cnt, (const float4*)x, (float4*)out, n);
}

// round 3
// speedup vs baseline: 1.5331x; 1.5331x over previous
#include <cuda_runtime.h>

#define MAXN 50000
#define MAXE 800000
#define DIM 128

// ---------------- scratch (allocation-free, 16B aligned) ----------------
__device__ float4 g_h1[MAXN * 32];
__device__ float4 g_h2[MAXN * 32];
__device__ float4 g_h3[MAXN * 32];
__device__ float g_as[MAXN * 2];
__device__ float g_ad[MAXN * 2];
__device__ int g_src[MAXE];
__device__ int g_dst[MAXE];
__device__ int g_csrc[MAXE];          // CSR: src ids grouped by dst
__device__ int g_rowptr[MAXN + 1];
__device__ int g_cursor[MAXN];
__device__ int g_is64;

// ---------------- dtype sniff: int64 indices have all-zero hi words ----------------
__global__ void detect_kernel(const unsigned int* __restrict__ raw, int E) {
    if (threadIdx.x != 0 || blockIdx.x != 0) return;
    int step = E / 64; if (step < 1) step = 1;
    int allz = 1;
    for (int k = 0; k < 64; k++) {
        long long j = 2LL * (long long)k * step + 1;
        if (j >= 2LL * E) break;
        if (raw[j] != 0u) { allz = 0; break; }
    }
    g_is64 = allz;
}

// ---------------- normalize indices to int32 + degree histogram ----------------
__global__ void convert_idx_kernel(const void* __restrict__ raw, int* __restrict__ s,
                                   int* __restrict__ d, int* __restrict__ cnt, int E) {
    int i = blockIdx.x * blockDim.x + threadIdx.x;
    if (i >= E) return;
    int sv, dv;
    if (g_is64) {
        const long long* p = (const long long*)raw;
        sv = (int)p[i]; dv = (int)p[E + i];
    } else {
        const int* p = (const int*)raw;
        sv = p[i]; dv = p[E + i];
    }
    s[i] = sv; d[i] = dv;
    atomicAdd(&cnt[dv], 1);
}

// ---------------- single-block exclusive scan: cnt -> rowptr, reset cursor ----------------
__global__ void scan_kernel(const int* __restrict__ cnt, int* __restrict__ rowptr,
                            int* __restrict__ cursor, int n) {
    __shared__ int part[1024];
    int t = threadIdx.x;
    int chunk = (n + 1023) >> 10;
    int b = t * chunk, e = min(b + chunk, n);
    int s = 0;
    for (int i = b; i < e; i++) s += cnt[i];
    part[t] = s;
    __syncthreads();
    #pragma unroll
    for (int off = 1; off < 1024; off <<= 1) {
        int v = (t >= off) ? part[t - off] : 0;
        __syncthreads();
        part[t] += v;
        __syncthreads();
    }
    int base = (t > 0) ? part[t - 1] : 0;
    for (int i = b; i < e; i++) {
        rowptr[i] = base;
        cursor[i] = base;
        base += cnt[i];
    }
    if (t == 1023) rowptr[n] = part[1023];
}

// ---------------- CSR fill: permute src ids into dst-grouped order ----------------
__global__ void fill_kernel(const int* __restrict__ s, const int* __restrict__ d,
                            int* __restrict__ cursor, int* __restrict__ csrc, int E) {
    int i = blockIdx.x * blockDim.x + threadIdx.x;
    if (i >= E) return;
    int pos = atomicAdd(&cursor[d[i]], 1);
    csrc[pos] = s[i];
}

// ---------------- GEMM + fused alpha logits ----------------
// H[n,128] = X[n,128] @ W[128,128]^T ; os/od[n,H] = per-head <H[n], a_src/a_dst>
template <int HEADS>
__global__ void gemm_kernel(const float* __restrict__ X, const float* __restrict__ W,
                            const float* __restrict__ a_src, const float* __restrict__ a_dst,
                            float* __restrict__ H, float* __restrict__ os,
                            float* __restrict__ od, int nrows) {
    extern __shared__ float sm[];
    float* xs = sm;               // [64][129]
    float* ws = sm + 64 * 129;    // [128][132]  ws[k][o] = W[o][k]
    int tid = threadIdx.x;
    int row0 = blockIdx.x * 64;

    #pragma unroll
    for (int i = 0; i < 32; i++) {
        int idx = tid + i * 256;
        int r = idx >> 7, k = idx & 127;
        float v = 0.f;
        if (row0 + r < nrows) v = X[(long long)(row0 + r) * DIM + k];
        xs[r * 129 + k] = v;
    }
    #pragma unroll
    for (int i = 0; i < 64; i++) {
        int idx = tid + i * 256;
        int o = idx >> 7, k = idx & 127;
        ws[k * 132 + o] = W[idx];
    }
    __syncthreads();

    int tx = tid & 15, ty = tid >> 4;
    float acc[4][8];
    #pragma unroll
    for (int i = 0; i < 4; i++)
        #pragma unroll
        for (int j = 0; j < 8; j++) acc[i][j] = 0.f;

    #pragma unroll 8
    for (int k = 0; k < 128; k++) {
        float aa[4];
        #pragma unroll
        for (int i = 0; i < 4; i++) aa[i] = xs[(ty * 4 + i) * 129 + k];
        float4 b0 = *(const float4*)&ws[k * 132 + tx * 4];
        float4 b1 = *(const float4*)&ws[k * 132 + 64 + tx * 4];
        float bb[8] = {b0.x, b0.y, b0.z, b0.w, b1.x, b1.y, b1.z, b1.w};
        #pragma unroll
        for (int i = 0; i < 4; i++)
            #pragma unroll
            for (int j = 0; j < 8; j++) acc[i][j] += aa[i] * bb[j];
    }

    float4 av0 = *(const float4*)&a_src[tx * 4];
    float4 av1 = *(const float4*)&a_src[64 + tx * 4];
    float4 bv0 = *(const float4*)&a_dst[tx * 4];
    float4 bv1 = *(const float4*)&a_dst[64 + tx * 4];

    #pragma unroll
    for (int i = 0; i < 4; i++) {
        int r = row0 + ty * 4 + i;
        bool ok = (r < nrows);
        if (ok) {
            float4 v0 = {acc[i][0], acc[i][1], acc[i][2], acc[i][3]};
            float4 v1 = {acc[i][4], acc[i][5], acc[i][6], acc[i][7]};
            *(float4*)&H[(long long)r * DIM + tx * 4] = v0;
            *(float4*)&H[(long long)r * DIM + 64 + tx * 4] = v1;
        }
        // alpha epilogue: partial dots, reduce over the 16 tx lanes (in-warp)
        float s0 = acc[i][0] * av0.x + acc[i][1] * av0.y + acc[i][2] * av0.z + acc[i][3] * av0.w;
        float s1 = acc[i][4] * av1.x + acc[i][5] * av1.y + acc[i][6] * av1.z + acc[i][7] * av1.w;
        float t0 = acc[i][0] * bv0.x + acc[i][1] * bv0.y + acc[i][2] * bv0.z + acc[i][3] * bv0.w;
        float t1 = acc[i][4] * bv1.x + acc[i][5] * bv1.y + acc[i][6] * bv1.z + acc[i][7] * bv1.w;
        if (HEADS == 1) { s0 += s1; t0 += t1; }
        #pragma unroll
        for (int off = 8; off >= 1; off >>= 1) {
            s0 += __shfl_xor_sync(0xffffffff, s0, off);
            t0 += __shfl_xor_sync(0xffffffff, t0, off);
            if (HEADS == 2) {
                s1 += __shfl_xor_sync(0xffffffff, s1, off);
                t1 += __shfl_xor_sync(0xffffffff, t1, off);
            }
        }
        if (tx == 0 && ok) {
            if (HEADS == 2) {
                os[r * 2] = s0; os[r * 2 + 1] = s1;
                od[r * 2] = t0; od[r * 2 + 1] = t1;
            } else {
                os[r] = s0; od[r] = t0;
            }
        }
    }
}

// ---------------- GAT gather: warp per dst node, self-loop folded, fused epilogue ----------------
template <int HEADS, bool RELU>
__global__ void gat_gather_kernel(const int* __restrict__ rowptr, const int* __restrict__ csrc,
                                  const float4* __restrict__ h, const float* __restrict__ as_,
                                  const float* __restrict__ ad_, const float* __restrict__ bias,
                                  float4* __restrict__ out, int n) {
    int g = blockIdx.x * blockDim.x + threadIdx.x;
    int d = g >> 5, lane = threadIdx.x & 31;
    if (d >= n) return;
    int head = (HEADS == 2) ? (lane >> 4) : 0;
    float adv = ad_[d * HEADS + head];

    float4 acc = {0.f, 0.f, 0.f, 0.f};
    float den = 0.f;

    // self loop
    {
        float a = as_[d * HEADS + head] + adv;
        float e = (a > 0.f) ? a : 0.2f * a;
        float w = __expf(e);
        float4 hv = h[d * 32 + lane];
        acc.x = w * hv.x; acc.y = w * hv.y; acc.z = w * hv.z; acc.w = w * hv.w;
        den = w;
    }

    int e0 = rowptr[d], e1 = rowptr[d + 1];
    for (int e = e0; e < e1; e++) {
        int s = csrc[e];
        float a = as_[s * HEADS + head] + adv;
        float lr = (a > 0.f) ? a : 0.2f * a;
        float w = __expf(lr);
        float4 hv = h[s * 32 + lane];
        acc.x += w * hv.x; acc.y += w * hv.y; acc.z += w * hv.z; acc.w += w * hv.w;
        den += w;
    }

    float inv = 1.f / den;
    float4 b = ((const float4*)bias)[lane];
    float4 r;
    r.x = acc.x * inv + b.x; r.y = acc.y * inv + b.y;
    r.z = acc.z * inv + b.z; r.w = acc.w * inv + b.w;
    if (RELU) {
        r.x = fmaxf(r.x, 0.f); r.y = fmaxf(r.y, 0.f);
        r.z = fmaxf(r.z, 0.f); r.w = fmaxf(r.w, 0.f);
    }
    out[d * 32 + lane] = r;
}

// ---------------- mean conv gather + residual + relu ----------------
__global__ void mean_gather_kernel(const int* __restrict__ rowptr, const int* __restrict__ csrc,
                                   const float4* __restrict__ h, const float4* __restrict__ x,
                                   float4* __restrict__ out, int n) {
    int g = blockIdx.x * blockDim.x + threadIdx.x;
    int d = g >> 5, lane = threadIdx.x & 31;
    if (d >= n) return;
    int e0 = rowptr[d], e1 = rowptr[d + 1];
    float4 acc = {0.f, 0.f, 0.f, 0.f};
    for (int e = e0; e < e1; e++) {
        float4 hv = h[csrc[e] * 32 + lane];
        acc.x += hv.x; acc.y += hv.y; acc.z += hv.z; acc.w += hv.w;
    }
    int cnt = e1 - e0;
    float inv = (cnt > 0) ? (1.f / (float)cnt) : 0.f;
    float4 xv = x[d * 32 + lane];
    float4 r;
    r.x = fmaxf(acc.x * inv + xv.x, 0.f);
    r.y = fmaxf(acc.y * inv + xv.y, 0.f);
    r.z = fmaxf(acc.z * inv + xv.z, 0.f);
    r.w = fmaxf(acc.w * inv + xv.w, 0.f);
    out[d * 32 + lane] = r;
}

// ---------------- launch ----------------
extern "C" void kernel_launch(void* const* d_in, const int* in_sizes, int n_in,
                              void* d_out, int out_size) {
    const float* x    = (const float*)d_in[0];
    const void*  ei   = d_in[1];
    const float* W1   = (const float*)d_in[2];
    const float* asv1 = (const float*)d_in[3];
    const float* adv1 = (const float*)d_in[4];
    const float* b1   = (const float*)d_in[5];
    const float* W2   = (const float*)d_in[6];
    const float* asv2 = (const float*)d_in[7];
    const float* adv2 = (const float*)d_in[8];
    const float* b2   = (const float*)d_in[9];
    float* out = (float*)d_out;

    int n = in_sizes[0] / DIM;
    int E = in_sizes[1] / 2;

    float4 *h1, *h2, *h3;
    float *as_, *ad_;
    int *srci, *dsti, *csrc, *rowptr, *cursor;
    cudaGetSymbolAddress((void**)&h1,     g_h1);
    cudaGetSymbolAddress((void**)&h2,     g_h2);
    cudaGetSymbolAddress((void**)&h3,     g_h3);
    cudaGetSymbolAddress((void**)&as_,    g_as);
    cudaGetSymbolAddress((void**)&ad_,    g_ad);
    cudaGetSymbolAddress((void**)&srci,   g_src);
    cudaGetSymbolAddress((void**)&dsti,   g_dst);
    cudaGetSymbolAddress((void**)&csrc,   g_csrc);
    cudaGetSymbolAddress((void**)&rowptr, g_rowptr);
    cudaGetSymbolAddress((void**)&cursor, g_cursor);

    const int gemm_smem = (64 * 129 + 128 * 132) * 4;
    cudaFuncSetAttribute(gemm_kernel<2>, cudaFuncAttributeMaxDynamicSharedMemorySize, gemm_smem);
    cudaFuncSetAttribute(gemm_kernel<1>, cudaFuncAttributeMaxDynamicSharedMemorySize, gemm_smem);

    int gemm_blocks  = (n + 63) / 64;
    int nwarp_blocks = (n * 32 + 255) / 256;
    int eth_blocks   = (E + 255) / 256;

    // ---- CSR build (by destination) ----
    detect_kernel<<<1, 32>>>((const unsigned int*)ei, E);
    cudaMemsetAsync(cursor, 0, (size_t)n * sizeof(int), 0);
    convert_idx_kernel<<<eth_blocks, 256>>>(ei, srci, dsti, cursor, E);
    scan_kernel<<<1, 1024>>>(cursor, rowptr, cursor, n);
    fill_kernel<<<eth_blocks, 256>>>(srci, dsti, cursor, csrc, E);

    // ---- GAT layer 1 (heads=2, ch=64) ----
    gemm_kernel<2><<<gemm_blocks, 256, gemm_smem>>>(x, W1, asv1, adv1, (float*)h1, as_, ad_, n);
    gat_gather_kernel<2, true><<<nwarp_blocks, 256>>>(rowptr, csrc, h1, as_, ad_, b1, h2, n);

    // ---- GAT layer 2 (heads=1, ch=128) ----
    gemm_kernel<1><<<gemm_blocks, 256, gemm_smem>>>((const float*)h2, W2, asv2, adv2,
                                                    (float*)h3, as_, ad_, n);
    gat_gather_kernel<1, false><<<nwarp_blocks, 256>>>(rowptr, csrc, h3, as_, ad_, b2, h1, n);

    // ---- mean conv + residual + relu ----
    mean_gather_kernel<<<nwarp_blocks, 256>>>(rowptr, csrc, h1, (const float4*)x,
                                              (float4*)out, n);
}

// round 4
// speedup vs baseline: 1.6468x; 1.0741x over previous
#include <cuda_runtime.h>

#define MAXN 50000
#define MAXE 800000
#define DIM 128

// ---------------- scratch (allocation-free, 16B aligned) ----------------
__device__ float4 g_h1[MAXN * 32];
__device__ float4 g_h2[MAXN * 32];
__device__ float4 g_h3[MAXN * 32];
__device__ float g_as[MAXN * 2];
__device__ float g_ad[MAXN * 2];
__device__ int g_src[MAXE];
__device__ int g_dst[MAXE];
__device__ int g_rank[MAXE];          // rank of edge within its dst bucket
__device__ int g_csrc[MAXE];          // CSR: src ids grouped by dst
__device__ int g_rowptr[MAXN + 1];
__device__ int g_cnt[MAXN];
__device__ int g_is64;

// ---------------- dtype sniff: int64 indices have all-zero hi words ----------------
__global__ void detect_kernel(const unsigned int* __restrict__ raw, int E) {
    if (threadIdx.x != 0 || blockIdx.x != 0) return;
    int step = E / 64; if (step < 1) step = 1;
    int allz = 1;
    for (int k = 0; k < 64; k++) {
        long long j = 2LL * (long long)k * step + 1;
        if (j >= 2LL * E) break;
        if (raw[j] != 0u) { allz = 0; break; }
    }
    g_is64 = allz;
}

// ---------------- normalize indices + degree histogram + per-edge rank ----------------
__global__ void convert_idx_kernel(const void* __restrict__ raw, int* __restrict__ s,
                                   int* __restrict__ d, int* __restrict__ rank,
                                   int* __restrict__ cnt, int E) {
    int i = blockIdx.x * blockDim.x + threadIdx.x;
    if (i >= E) return;
    int sv, dv;
    if (g_is64) {
        const int2* p = (const int2*)raw;   // int64 little-endian: .x = low word
        sv = p[i].x; dv = p[E + i].x;
    } else {
        const int* p = (const int*)raw;
        sv = p[i]; dv = p[E + i];
    }
    s[i] = sv; d[i] = dv;
    rank[i] = atomicAdd(&cnt[dv], 1);     // rank within dst bucket (free byproduct)
}

// ---------------- single-block exclusive scan: cnt -> rowptr ----------------
__global__ void scan_kernel(const int* __restrict__ cnt, int* __restrict__ rowptr, int n) {
    __shared__ int part[1024];
    int t = threadIdx.x;
    int chunk = (n + 1023) >> 10;
    int b = t * chunk, e = min(b + chunk, n);
    int s = 0;
    for (int i = b; i < e; i++) s += cnt[i];
    part[t] = s;
    __syncthreads();
    #pragma unroll
    for (int off = 1; off < 1024; off <<= 1) {
        int v = (t >= off) ? part[t - off] : 0;
        __syncthreads();
        part[t] += v;
        __syncthreads();
    }
    int base = (t > 0) ? part[t - 1] : 0;
    for (int i = b; i < e; i++) {
        rowptr[i] = base;
        base += cnt[i];
    }
    if (t == 1023) rowptr[n] = part[1023];
}

// ---------------- CSR fill: pure scatter, no atomics ----------------
__global__ void fill_kernel(const int* __restrict__ s, const int* __restrict__ d,
                            const int* __restrict__ rank, const int* __restrict__ rowptr,
                            int* __restrict__ csrc, int E) {
    int i = blockIdx.x * blockDim.x + threadIdx.x;
    if (i >= E) return;
    csrc[rowptr[d[i]] + rank[i]] = s[i];
}

// ---------------- GEMM + fused alpha logits ----------------
// H[n,128] = X[n,128] @ W[128,128]^T ; os/od[n,H] = per-head <H[n], a_src/a_dst>
template <int HEADS>
__global__ void gemm_kernel(const float* __restrict__ X, const float* __restrict__ W,
                            const float* __restrict__ a_src, const float* __restrict__ a_dst,
                            float* __restrict__ H, float* __restrict__ os,
                            float* __restrict__ od, int nrows) {
    extern __shared__ float sm[];
    float* xs = sm;               // [64][129]
    float* ws = sm + 64 * 129;    // [128][132]  ws[k][o] = W[o][k]
    int tid = threadIdx.x;
    int row0 = blockIdx.x * 64;

    #pragma unroll
    for (int i = 0; i < 32; i++) {
        int idx = tid + i * 256;
        int r = idx >> 7, k = idx & 127;
        float v = 0.f;
        if (row0 + r < nrows) v = X[(long long)(row0 + r) * DIM + k];
        xs[r * 129 + k] = v;
    }
    #pragma unroll
    for (int i = 0; i < 64; i++) {
        int idx = tid + i * 256;
        int o = idx >> 7, k = idx & 127;
        ws[k * 132 + o] = W[idx];
    }
    __syncthreads();

    int tx = tid & 15, ty = tid >> 4;
    float acc[4][8];
    #pragma unroll
    for (int i = 0; i < 4; i++)
        #pragma unroll
        for (int j = 0; j < 8; j++) acc[i][j] = 0.f;

    #pragma unroll 8
    for (int k = 0; k < 128; k++) {
        float aa[4];
        #pragma unroll
        for (int i = 0; i < 4; i++) aa[i] = xs[(ty * 4 + i) * 129 + k];
        float4 b0 = *(const float4*)&ws[k * 132 + tx * 4];
        float4 b1 = *(const float4*)&ws[k * 132 + 64 + tx * 4];
        float bb[8] = {b0.x, b0.y, b0.z, b0.w, b1.x, b1.y, b1.z, b1.w};
        #pragma unroll
        for (int i = 0; i < 4; i++)
            #pragma unroll
            for (int j = 0; j < 8; j++) acc[i][j] += aa[i] * bb[j];
    }

    float4 av0 = *(const float4*)&a_src[tx * 4];
    float4 av1 = *(const float4*)&a_src[64 + tx * 4];
    float4 bv0 = *(const float4*)&a_dst[tx * 4];
    float4 bv1 = *(const float4*)&a_dst[64 + tx * 4];

    #pragma unroll
    for (int i = 0; i < 4; i++) {
        int r = row0 + ty * 4 + i;
        bool ok = (r < nrows);
        if (ok) {
            float4 v0 = {acc[i][0], acc[i][1], acc[i][2], acc[i][3]};
            float4 v1 = {acc[i][4], acc[i][5], acc[i][6], acc[i][7]};
            *(float4*)&H[(long long)r * DIM + tx * 4] = v0;
            *(float4*)&H[(long long)r * DIM + 64 + tx * 4] = v1;
        }
        float s0 = acc[i][0] * av0.x + acc[i][1] * av0.y + acc[i][2] * av0.z + acc[i][3] * av0.w;
        float s1 = acc[i][4] * av1.x + acc[i][5] * av1.y + acc[i][6] * av1.z + acc[i][7] * av1.w;
        float t0 = acc[i][0] * bv0.x + acc[i][1] * bv0.y + acc[i][2] * bv0.z + acc[i][3] * bv0.w;
        float t1 = acc[i][4] * bv1.x + acc[i][5] * bv1.y + acc[i][6] * bv1.z + acc[i][7] * bv1.w;
        if (HEADS == 1) { s0 += s1; t0 += t1; }
        #pragma unroll
        for (int off = 8; off >= 1; off >>= 1) {
            s0 += __shfl_xor_sync(0xffffffff, s0, off);
            t0 += __shfl_xor_sync(0xffffffff, t0, off);
            if (HEADS == 2) {
                s1 += __shfl_xor_sync(0xffffffff, s1, off);
                t1 += __shfl_xor_sync(0xffffffff, t1, off);
            }
        }
        if (tx == 0 && ok) {
            if (HEADS == 2) {
                os[r * 2] = s0; os[r * 2 + 1] = s1;
                od[r * 2] = t0; od[r * 2 + 1] = t1;
            } else {
                os[r] = s0; od[r] = t0;
            }
        }
    }
}

// ---------------- GAT gather: warp per dst node, x4 unrolled for MLP ----------------
template <int HEADS, bool RELU>
__global__ void gat_gather_kernel(const int* __restrict__ rowptr, const int* __restrict__ csrc,
                                  const float4* __restrict__ h, const float* __restrict__ as_,
                                  const float* __restrict__ ad_, const float* __restrict__ bias,
                                  float4* __restrict__ out, int n) {
    int g = blockIdx.x * blockDim.x + threadIdx.x;
    int d = g >> 5, lane = threadIdx.x & 31;
    if (d >= n) return;
    int head = (HEADS == 2) ? (lane >> 4) : 0;
    float adv = ad_[d * HEADS + head];

    float4 acc = {0.f, 0.f, 0.f, 0.f};
    float den = 0.f;

    // self loop
    {
        float a = as_[d * HEADS + head] + adv;
        float lr = (a > 0.f) ? a : 0.2f * a;
        float w = __expf(lr);
        float4 hv = h[d * 32 + lane];
        acc.x = w * hv.x; acc.y = w * hv.y; acc.z = w * hv.z; acc.w = w * hv.w;
        den = w;
    }

    int e0 = rowptr[d], e1 = rowptr[d + 1];
    int e = e0;
    for (; e + 4 <= e1; e += 4) {
        int s0 = csrc[e], s1 = csrc[e + 1], s2 = csrc[e + 2], s3 = csrc[e + 3];
        float a0 = as_[s0 * HEADS + head];
        float a1 = as_[s1 * HEADS + head];
        float a2 = as_[s2 * HEADS + head];
        float a3 = as_[s3 * HEADS + head];
        float4 h0 = h[s0 * 32 + lane];
        float4 h1v = h[s1 * 32 + lane];
        float4 h2v = h[s2 * 32 + lane];
        float4 h3v = h[s3 * 32 + lane];
        a0 += adv; a1 += adv; a2 += adv; a3 += adv;
        a0 = (a0 > 0.f) ? a0 : 0.2f * a0;
        a1 = (a1 > 0.f) ? a1 : 0.2f * a1;
        a2 = (a2 > 0.f) ? a2 : 0.2f * a2;
        a3 = (a3 > 0.f) ? a3 : 0.2f * a3;
        float w0 = __expf(a0), w1 = __expf(a1), w2 = __expf(a2), w3 = __expf(a3);
        acc.x += w0 * h0.x + w1 * h1v.x + w2 * h2v.x + w3 * h3v.x;
        acc.y += w0 * h0.y + w1 * h1v.y + w2 * h2v.y + w3 * h3v.y;
        acc.z += w0 * h0.z + w1 * h1v.z + w2 * h2v.z + w3 * h3v.z;
        acc.w += w0 * h0.w + w1 * h1v.w + w2 * h2v.w + w3 * h3v.w;
        den += (w0 + w1) + (w2 + w3);
    }
    for (; e < e1; e++) {
        int s = csrc[e];
        float a = as_[s * HEADS + head] + adv;
        float lr = (a > 0.f) ? a : 0.2f * a;
        float w = __expf(lr);
        float4 hv = h[s * 32 + lane];
        acc.x += w * hv.x; acc.y += w * hv.y; acc.z += w * hv.z; acc.w += w * hv.w;
        den += w;
    }

    float inv = 1.f / den;
    float4 b = ((const float4*)bias)[lane];
    float4 r;
    r.x = acc.x * inv + b.x; r.y = acc.y * inv + b.y;
    r.z = acc.z * inv + b.z; r.w = acc.w * inv + b.w;
    if (RELU) {
        r.x = fmaxf(r.x, 0.f); r.y = fmaxf(r.y, 0.f);
        r.z = fmaxf(r.z, 0.f); r.w = fmaxf(r.w, 0.f);
    }
    out[d * 32 + lane] = r;
}

// ---------------- mean conv gather + residual + relu (x4 unrolled) ----------------
__global__ void mean_gather_kernel(const int* __restrict__ rowptr, const int* __restrict__ csrc,
                                   const float4* __restrict__ h, const float4* __restrict__ x,
                                   float4* __restrict__ out, int n) {
    int g = blockIdx.x * blockDim.x + threadIdx.x;
    int d = g >> 5, lane = threadIdx.x & 31;
    if (d >= n) return;
    int e0 = rowptr[d], e1 = rowptr[d + 1];
    float4 acc = {0.f, 0.f, 0.f, 0.f};
    int e = e0;
    for (; e + 4 <= e1; e += 4) {
        int s0 = csrc[e], s1 = csrc[e + 1], s2 = csrc[e + 2], s3 = csrc[e + 3];
        float4 h0 = h[s0 * 32 + lane];
        float4 h1v = h[s1 * 32 + lane];
        float4 h2v = h[s2 * 32 + lane];
        float4 h3v = h[s3 * 32 + lane];
        acc.x += (h0.x + h1v.x) + (h2v.x + h3v.x);
        acc.y += (h0.y + h1v.y) + (h2v.y + h3v.y);
        acc.z += (h0.z + h1v.z) + (h2v.z + h3v.z);
        acc.w += (h0.w + h1v.w) + (h2v.w + h3v.w);
    }
    for (; e < e1; e++) {
        float4 hv = h[csrc[e] * 32 + lane];
        acc.x += hv.x; acc.y += hv.y; acc.z += hv.z; acc.w += hv.w;
    }
    int cnt = e1 - e0;
    float inv = (cnt > 0) ? (1.f / (float)cnt) : 0.f;
    float4 xv = x[d * 32 + lane];
    float4 r;
    r.x = fmaxf(acc.x * inv + xv.x, 0.f);
    r.y = fmaxf(acc.y * inv + xv.y, 0.f);
    r.z = fmaxf(acc.z * inv + xv.z, 0.f);
    r.w = fmaxf(acc.w * inv + xv.w, 0.f);
    out[d * 32 + lane] = r;
}

// ---------------- launch ----------------
extern "C" void kernel_launch(void* const* d_in, const int* in_sizes, int n_in,
                              void* d_out, int out_size) {
    const float* x    = (const float*)d_in[0];
    const void*  ei   = d_in[1];
    const float* W1   = (const float*)d_in[2];
    const float* asv1 = (const float*)d_in[3];
    const float* adv1 = (const float*)d_in[4];
    const float* b1   = (const float*)d_in[5];
    const float* W2   = (const float*)d_in[6];
    const float* asv2 = (const float*)d_in[7];
    const float* adv2 = (const float*)d_in[8];
    const float* b2   = (const float*)d_in[9];
    float* out = (float*)d_out;

    int n = in_sizes[0] / DIM;
    int E = in_sizes[1] / 2;

    float4 *h1, *h2, *h3;
    float *as_, *ad_;
    int *srci, *dsti, *rank, *csrc, *rowptr, *cnt;
    cudaGetSymbolAddress((void**)&h1,     g_h1);
    cudaGetSymbolAddress((void**)&h2,     g_h2);
    cudaGetSymbolAddress((void**)&h3,     g_h3);
    cudaGetSymbolAddress((void**)&as_,    g_as);
    cudaGetSymbolAddress((void**)&ad_,    g_ad);
    cudaGetSymbolAddress((void**)&srci,   g_src);
    cudaGetSymbolAddress((void**)&dsti,   g_dst);
    cudaGetSymbolAddress((void**)&rank,   g_rank);
    cudaGetSymbolAddress((void**)&csrc,   g_csrc);
    cudaGetSymbolAddress((void**)&rowptr, g_rowptr);
    cudaGetSymbolAddress((void**)&cnt,    g_cnt);

    const int gemm_smem = (64 * 129 + 128 * 132) * 4;
    cudaFuncSetAttribute(gemm_kernel<2>, cudaFuncAttributeMaxDynamicSharedMemorySize, gemm_smem);
    cudaFuncSetAttribute(gemm_kernel<1>, cudaFuncAttributeMaxDynamicSharedMemorySize, gemm_smem);

    int gemm_blocks  = (n + 63) / 64;
    int nwarp_blocks = (n * 32 + 255) / 256;
    int eth_blocks   = (E + 255) / 256;

    // ---- CSR build (by destination) ----
    detect_kernel<<<1, 32>>>((const unsigned int*)ei, E);
    cudaMemsetAsync(cnt, 0, (size_t)n * sizeof(int), 0);
    convert_idx_kernel<<<eth_blocks, 256>>>(ei, srci, dsti, rank, cnt, E);
    scan_kernel<<<1, 1024>>>(cnt, rowptr, n);
    fill_kernel<<<eth_blocks, 256>>>(srci, dsti, rank, rowptr, csrc, E);

    // ---- GAT layer 1 (heads=2, ch=64) ----
    gemm_kernel<2><<<gemm_blocks, 256, gemm_smem>>>(x, W1, asv1, adv1, (float*)h1, as_, ad_, n);
    gat_gather_kernel<2, true><<<nwarp_blocks, 256>>>(rowptr, csrc, h1, as_, ad_, b1, h2, n);

    // ---- GAT layer 2 (heads=1, ch=128) ----
    gemm_kernel<1><<<gemm_blocks, 256, gemm_smem>>>((const float*)h2, W2, asv2, adv2,
                                                    (float*)h3, as_, ad_, n);
    gat_gather_kernel<1, false><<<nwarp_blocks, 256>>>(rowptr, csrc, h3, as_, ad_, b2, h1, n);

    // ---- mean conv + residual + relu ----
    mean_gather_kernel<<<nwarp_blocks, 256>>>(rowptr, csrc, h1, (const float4*)x,
                                              (float4*)out, n);
}

// round 5
// speedup vs baseline: 1.7137x; 1.0406x over previous
#include <cuda_runtime.h>
#include <cuda_fp16.h>

#define MAXN 50000
#define MAXE 800000
#define DIM 128

// ---------------- scratch (allocation-free, 16B/8B aligned) ----------------
__device__ uint2  g_h1[MAXN * 32];   // half4 rows: GEMM1 out (GAT1 gather input)
__device__ float4 g_h2[MAXN * 32];   // fp32: GAT1 out (GEMM2 input)
__device__ uint2  g_h3[MAXN * 32];   // half4: GEMM2 out (GAT2 gather input)
__device__ uint2  g_h4[MAXN * 32];   // half4: GAT2 out (mean-conv input)
__device__ float g_as[MAXN * 2];
__device__ float g_ad[MAXN * 2];
__device__ int g_src[MAXE];
__device__ int g_dst[MAXE];
__device__ int g_rank[MAXE];
__device__ int g_csrc[MAXE];
__device__ int g_rowptr[MAXN + 1];
__device__ int g_cnt[MAXN];
__device__ int g_is64;

// ---------------- half4 <-> float4 ----------------
__device__ __forceinline__ float4 h4f4(uint2 u) {
    half2 a = *reinterpret_cast<half2*>(&u.x);
    half2 b = *reinterpret_cast<half2*>(&u.y);
    float2 fa = __half22float2(a), fb = __half22float2(b);
    float4 r; r.x = fa.x; r.y = fa.y; r.z = fb.x; r.w = fb.y; return r;
}
__device__ __forceinline__ uint2 f4h4(float4 v) {
    half2 a = __floats2half2_rn(v.x, v.y);
    half2 b = __floats2half2_rn(v.z, v.w);
    uint2 u;
    u.x = *reinterpret_cast<unsigned*>(&a);
    u.y = *reinterpret_cast<unsigned*>(&b);
    return u;
}

// ---------------- dtype sniff ----------------
__global__ void detect_kernel(const unsigned int* __restrict__ raw, int E) {
    if (threadIdx.x != 0 || blockIdx.x != 0) return;
    int step = E / 64; if (step < 1) step = 1;
    int allz = 1;
    for (int k = 0; k < 64; k++) {
        long long j = 2LL * (long long)k * step + 1;
        if (j >= 2LL * E) break;
        if (raw[j] != 0u) { allz = 0; break; }
    }
    g_is64 = allz;
}

// ---------------- normalize indices + histogram + rank (4 edges/thread) ----------------
__global__ void convert_idx_kernel(const void* __restrict__ raw, int* __restrict__ s,
                                   int* __restrict__ d, int* __restrict__ rank,
                                   int* __restrict__ cnt, int E) {
    int i0 = (blockIdx.x * blockDim.x + threadIdx.x) * 4;
    if (i0 >= E) return;
    int m = min(4, E - i0);
    int sv[4], dv[4];
    if (g_is64) {
        const int2* p = (const int2*)raw;
        #pragma unroll
        for (int k = 0; k < 4; k++) if (k < m) { sv[k] = p[i0 + k].x; dv[k] = p[E + i0 + k].x; }
    } else {
        const int* p = (const int*)raw;
        #pragma unroll
        for (int k = 0; k < 4; k++) if (k < m) { sv[k] = p[i0 + k]; dv[k] = p[E + i0 + k]; }
    }
    #pragma unroll
    for (int k = 0; k < 4; k++) if (k < m) {
        s[i0 + k] = sv[k];
        d[i0 + k] = dv[k];
        rank[i0 + k] = atomicAdd(&cnt[dv[k]], 1);
    }
}

// ---------------- single-block exclusive scan ----------------
__global__ void scan_kernel(const int* __restrict__ cnt, int* __restrict__ rowptr, int n) {
    __shared__ int part[1024];
    int t = threadIdx.x;
    int chunk = (n + 1023) >> 10;
    int b = t * chunk, e = min(b + chunk, n);
    int s = 0;
    for (int i = b; i < e; i++) s += cnt[i];
    part[t] = s;
    __syncthreads();
    #pragma unroll
    for (int off = 1; off < 1024; off <<= 1) {
        int v = (t >= off) ? part[t - off] : 0;
        __syncthreads();
        part[t] += v;
        __syncthreads();
    }
    int base = (t > 0) ? part[t - 1] : 0;
    for (int i = b; i < e; i++) { rowptr[i] = base; base += cnt[i]; }
    if (t == 1023) rowptr[n] = part[1023];
}

// ---------------- CSR fill: pure scatter, 4 edges/thread ----------------
__global__ void fill_kernel(const int* __restrict__ s, const int* __restrict__ d,
                            const int* __restrict__ rank, const int* __restrict__ rowptr,
                            int* __restrict__ csrc, int E) {
    int i0 = (blockIdx.x * blockDim.x + threadIdx.x) * 4;
    if (i0 >= E) return;
    int m = min(4, E - i0);
    int dv[4], rv[4], sv[4], rp[4];
    #pragma unroll
    for (int k = 0; k < 4; k++) if (k < m) { dv[k] = d[i0 + k]; rv[k] = rank[i0 + k]; sv[k] = s[i0 + k]; }
    #pragma unroll
    for (int k = 0; k < 4; k++) if (k < m) rp[k] = rowptr[dv[k]];
    #pragma unroll
    for (int k = 0; k < 4; k++) if (k < m) csrc[rp[k] + rv[k]] = sv[k];
}

// ---------------- GEMM + fused alpha logits, half output ----------------
// Hh[n,128](half) = X[n,128] @ W[128,128]^T ; os/od = per-head logits
template <int HEADS>
__global__ void gemm_kernel(const float* __restrict__ X, const float* __restrict__ W,
                            const float* __restrict__ a_src, const float* __restrict__ a_dst,
                            uint2* __restrict__ Hh, float* __restrict__ os,
                            float* __restrict__ od, int nrows) {
    extern __shared__ float sm[];
    float* xs = sm;               // [64][129]
    float* ws = sm + 64 * 129;    // [128][132]
    int tid = threadIdx.x;
    int row0 = blockIdx.x * 64;

    #pragma unroll
    for (int i = 0; i < 32; i++) {
        int idx = tid + i * 256;
        int r = idx >> 7, k = idx & 127;
        float v = 0.f;
        if (row0 + r < nrows) v = X[(long long)(row0 + r) * DIM + k];
        xs[r * 129 + k] = v;
    }
    #pragma unroll
    for (int i = 0; i < 64; i++) {
        int idx = tid + i * 256;
        int o = idx >> 7, k = idx & 127;
        ws[k * 132 + o] = W[idx];
    }
    __syncthreads();

    int tx = tid & 15, ty = tid >> 4;
    float acc[4][8];
    #pragma unroll
    for (int i = 0; i < 4; i++)
        #pragma unroll
        for (int j = 0; j < 8; j++) acc[i][j] = 0.f;

    #pragma unroll 8
    for (int k = 0; k < 128; k++) {
        float aa[4];
        #pragma unroll
        for (int i = 0; i < 4; i++) aa[i] = xs[(ty * 4 + i) * 129 + k];
        float4 b0 = *(const float4*)&ws[k * 132 + tx * 4];
        float4 b1 = *(const float4*)&ws[k * 132 + 64 + tx * 4];
        float bb[8] = {b0.x, b0.y, b0.z, b0.w, b1.x, b1.y, b1.z, b1.w};
        #pragma unroll
        for (int i = 0; i < 4; i++)
            #pragma unroll
            for (int j = 0; j < 8; j++) acc[i][j] += aa[i] * bb[j];
    }

    float4 av0 = *(const float4*)&a_src[tx * 4];
    float4 av1 = *(const float4*)&a_src[64 + tx * 4];
    float4 bv0 = *(const float4*)&a_dst[tx * 4];
    float4 bv1 = *(const float4*)&a_dst[64 + tx * 4];

    #pragma unroll
    for (int i = 0; i < 4; i++) {
        int r = row0 + ty * 4 + i;
        bool ok = (r < nrows);
        if (ok) {
            float4 v0 = {acc[i][0], acc[i][1], acc[i][2], acc[i][3]};
            float4 v1 = {acc[i][4], acc[i][5], acc[i][6], acc[i][7]};
            Hh[(long long)r * 32 + tx]      = f4h4(v0);
            Hh[(long long)r * 32 + 16 + tx] = f4h4(v1);
        }
        float s0 = acc[i][0] * av0.x + acc[i][1] * av0.y + acc[i][2] * av0.z + acc[i][3] * av0.w;
        float s1 = acc[i][4] * av1.x + acc[i][5] * av1.y + acc[i][6] * av1.z + acc[i][7] * av1.w;
        float t0 = acc[i][0] * bv0.x + acc[i][1] * bv0.y + acc[i][2] * bv0.z + acc[i][3] * bv0.w;
        float t1 = acc[i][4] * bv1.x + acc[i][5] * bv1.y + acc[i][6] * bv1.z + acc[i][7] * bv1.w;
        if (HEADS == 1) { s0 += s1; t0 += t1; }
        #pragma unroll
        for (int off = 8; off >= 1; off >>= 1) {
            s0 += __shfl_xor_sync(0xffffffff, s0, off);
            t0 += __shfl_xor_sync(0xffffffff, t0, off);
            if (HEADS == 2) {
                s1 += __shfl_xor_sync(0xffffffff, s1, off);
                t1 += __shfl_xor_sync(0xffffffff, t1, off);
            }
        }
        if (tx == 0 && ok) {
            if (HEADS == 2) {
                os[r * 2] = s0; os[r * 2 + 1] = s1;
                od[r * 2] = t0; od[r * 2 + 1] = t1;
            } else {
                os[r] = s0; od[r] = t0;
            }
        }
    }
}

// ---------------- GAT gather: warp/dst node, half input, x4 unroll ----------------
// OUT_HALF: write half4 (for mean-conv input) else fp32 float4 (for next GEMM)
template <int HEADS, bool RELU, bool OUT_HALF>
__global__ void gat_gather_kernel(const int* __restrict__ rowptr, const int* __restrict__ csrc,
                                  const uint2* __restrict__ h, const float* __restrict__ as_,
                                  const float* __restrict__ ad_, const float* __restrict__ bias,
                                  float4* __restrict__ outf, uint2* __restrict__ outh, int n) {
    int g = blockIdx.x * blockDim.x + threadIdx.x;
    int d = g >> 5, lane = threadIdx.x & 31;
    if (d >= n) return;
    int head = (HEADS == 2) ? (lane >> 4) : 0;
    float adv = ad_[d * HEADS + head];

    float4 acc;
    float den;
    {   // self loop
        float a = as_[d * HEADS + head] + adv;
        float lr = (a > 0.f) ? a : 0.2f * a;
        float w = __expf(lr);
        float4 hv = h4f4(h[d * 32 + lane]);
        acc.x = w * hv.x; acc.y = w * hv.y; acc.z = w * hv.z; acc.w = w * hv.w;
        den = w;
    }

    int e0 = rowptr[d], e1 = rowptr[d + 1];
    int e = e0;
    for (; e + 4 <= e1; e += 4) {
        int s0 = csrc[e], s1 = csrc[e + 1], s2 = csrc[e + 2], s3 = csrc[e + 3];
        float a0 = as_[s0 * HEADS + head];
        float a1 = as_[s1 * HEADS + head];
        float a2 = as_[s2 * HEADS + head];
        float a3 = as_[s3 * HEADS + head];
        uint2 u0 = h[s0 * 32 + lane];
        uint2 u1 = h[s1 * 32 + lane];
        uint2 u2 = h[s2 * 32 + lane];
        uint2 u3 = h[s3 * 32 + lane];
        a0 += adv; a1 += adv; a2 += adv; a3 += adv;
        a0 = (a0 > 0.f) ? a0 : 0.2f * a0;
        a1 = (a1 > 0.f) ? a1 : 0.2f * a1;
        a2 = (a2 > 0.f) ? a2 : 0.2f * a2;
        a3 = (a3 > 0.f) ? a3 : 0.2f * a3;
        float w0 = __expf(a0), w1 = __expf(a1), w2 = __expf(a2), w3 = __expf(a3);
        float4 h0 = h4f4(u0), h1v = h4f4(u1), h2v = h4f4(u2), h3v = h4f4(u3);
        acc.x += w0 * h0.x + w1 * h1v.x + w2 * h2v.x + w3 * h3v.x;
        acc.y += w0 * h0.y + w1 * h1v.y + w2 * h2v.y + w3 * h3v.y;
        acc.z += w0 * h0.z + w1 * h1v.z + w2 * h2v.z + w3 * h3v.z;
        acc.w += w0 * h0.w + w1 * h1v.w + w2 * h2v.w + w3 * h3v.w;
        den += (w0 + w1) + (w2 + w3);
    }
    for (; e < e1; e++) {
        int s = csrc[e];
        float a = as_[s * HEADS + head] + adv;
        float lr = (a > 0.f) ? a : 0.2f * a;
        float w = __expf(lr);
        float4 hv = h4f4(h[s * 32 + lane]);
        acc.x += w * hv.x; acc.y += w * hv.y; acc.z += w * hv.z; acc.w += w * hv.w;
        den += w;
    }

    float inv = 1.f / den;
    float4 b = ((const float4*)bias)[lane];
    float4 r;
    r.x = acc.x * inv + b.x; r.y = acc.y * inv + b.y;
    r.z = acc.z * inv + b.z; r.w = acc.w * inv + b.w;
    if (RELU) {
        r.x = fmaxf(r.x, 0.f); r.y = fmaxf(r.y, 0.f);
        r.z = fmaxf(r.z, 0.f); r.w = fmaxf(r.w, 0.f);
    }
    if (OUT_HALF) outh[d * 32 + lane] = f4h4(r);
    else          outf[d * 32 + lane] = r;
}

// ---------------- mean conv gather (half in) + residual + relu ----------------
__global__ void mean_gather_kernel(const int* __restrict__ rowptr, const int* __restrict__ csrc,
                                   const uint2* __restrict__ h, const float4* __restrict__ x,
                                   float4* __restrict__ out, int n) {
    int g = blockIdx.x * blockDim.x + threadIdx.x;
    int d = g >> 5, lane = threadIdx.x & 31;
    if (d >= n) return;
    int e0 = rowptr[d], e1 = rowptr[d + 1];
    float4 acc = {0.f, 0.f, 0.f, 0.f};
    int e = e0;
    for (; e + 4 <= e1; e += 4) {
        int s0 = csrc[e], s1 = csrc[e + 1], s2 = csrc[e + 2], s3 = csrc[e + 3];
        float4 h0 = h4f4(h[s0 * 32 + lane]);
        float4 h1v = h4f4(h[s1 * 32 + lane]);
        float4 h2v = h4f4(h[s2 * 32 + lane]);
        float4 h3v = h4f4(h[s3 * 32 + lane]);
        acc.x += (h0.x + h1v.x) + (h2v.x + h3v.x);
        acc.y += (h0.y + h1v.y) + (h2v.y + h3v.y);
        acc.z += (h0.z + h1v.z) + (h2v.z + h3v.z);
        acc.w += (h0.w + h1v.w) + (h2v.w + h3v.w);
    }
    for (; e < e1; e++) {
        float4 hv = h4f4(h[csrc[e] * 32 + lane]);
        acc.x += hv.x; acc.y += hv.y; acc.z += hv.z; acc.w += hv.w;
    }
    int cnt = e1 - e0;
    float inv = (cnt > 0) ? (1.f / (float)cnt) : 0.f;
    float4 xv = x[d * 32 + lane];
    float4 r;
    r.x = fmaxf(acc.x * inv + xv.x, 0.f);
    r.y = fmaxf(acc.y * inv + xv.y, 0.f);
    r.z = fmaxf(acc.z * inv + xv.z, 0.f);
    r.w = fmaxf(acc.w * inv + xv.w, 0.f);
    out[d * 32 + lane] = r;
}

// ---------------- launch ----------------
extern "C" void kernel_launch(void* const* d_in, const int* in_sizes, int n_in,
                              void* d_out, int out_size) {
    const float* x    = (const float*)d_in[0];
    const void*  ei   = d_in[1];
    const float* W1   = (const float*)d_in[2];
    const float* asv1 = (const float*)d_in[3];
    const float* adv1 = (const float*)d_in[4];
    const float* b1   = (const float*)d_in[5];
    const float* W2   = (const float*)d_in[6];
    const float* asv2 = (const float*)d_in[7];
    const float* adv2 = (const float*)d_in[8];
    const float* b2   = (const float*)d_in[9];
    float* out = (float*)d_out;

    int n = in_sizes[0] / DIM;
    int E = in_sizes[1] / 2;

    uint2 *h1, *h3, *h4;
    float4 *h2;
    float *as_, *ad_;
    int *srci, *dsti, *rank, *csrc, *rowptr, *cnt;
    cudaGetSymbolAddress((void**)&h1,     g_h1);
    cudaGetSymbolAddress((void**)&h2,     g_h2);
    cudaGetSymbolAddress((void**)&h3,     g_h3);
    cudaGetSymbolAddress((void**)&h4,     g_h4);
    cudaGetSymbolAddress((void**)&as_,    g_as);
    cudaGetSymbolAddress((void**)&ad_,    g_ad);
    cudaGetSymbolAddress((void**)&srci,   g_src);
    cudaGetSymbolAddress((void**)&dsti,   g_dst);
    cudaGetSymbolAddress((void**)&rank,   g_rank);
    cudaGetSymbolAddress((void**)&csrc,   g_csrc);
    cudaGetSymbolAddress((void**)&rowptr, g_rowptr);
    cudaGetSymbolAddress((void**)&cnt,    g_cnt);

    const int gemm_smem = (64 * 129 + 128 * 132) * 4;
    cudaFuncSetAttribute(gemm_kernel<2>, cudaFuncAttributeMaxDynamicSharedMemorySize, gemm_smem);
    cudaFuncSetAttribute(gemm_kernel<1>, cudaFuncAttributeMaxDynamicSharedMemorySize, gemm_smem);

    int gemm_blocks  = (n + 63) / 64;
    int nwarp_blocks = (n * 32 + 255) / 256;
    int e4_blocks    = ((E + 3) / 4 + 255) / 256;

    // ---- CSR build (by destination) ----
    detect_kernel<<<1, 32>>>((const unsigned int*)ei, E);
    cudaMemsetAsync(cnt, 0, (size_t)n * sizeof(int), 0);
    convert_idx_kernel<<<e4_blocks, 256>>>(ei, srci, dsti, rank, cnt, E);
    scan_kernel<<<1, 1024>>>(cnt, rowptr, n);
    fill_kernel<<<e4_blocks, 256>>>(srci, dsti, rank, rowptr, csrc, E);

    // ---- GAT layer 1 (heads=2, ch=64) ----
    gemm_kernel<2><<<gemm_blocks, 256, gemm_smem>>>(x, W1, asv1, adv1, h1, as_, ad_, n);
    gat_gather_kernel<2, true, false><<<nwarp_blocks, 256>>>(rowptr, csrc, h1, as_, ad_, b1,
                                                             h2, nullptr, n);

    // ---- GAT layer 2 (heads=1, ch=128) ----
    gemm_kernel<1><<<gemm_blocks, 256, gemm_smem>>>((const float*)h2, W2, asv2, adv2,
                                                    h3, as_, ad_, n);
    gat_gather_kernel<1, false, true><<<nwarp_blocks, 256>>>(rowptr, csrc, h3, as_, ad_, b2,
                                                             nullptr, h4, n);

    // ---- mean conv + residual + relu ----
    mean_gather_kernel<<<nwarp_blocks, 256>>>(rowptr, csrc, h4, (const float4*)x,
                                              (float4*)out, n);
}

// round 6
// speedup vs baseline: 2.1221x; 1.2383x over previous
#include <cuda_runtime.h>
#include <cuda_fp16.h>
#include <mma.h>
using namespace nvcuda;

#define MAXN 50000
#define NPAD 50048          // padded rows so 128-row GEMM tiles store unguarded
#define MAXE 800000
#define DIM 128

// ---------------- scratch (allocation-free) ----------------
__device__ uint2  g_xh[NPAD * 32];   // half4: x in fp16 (GEMM1 A)
__device__ uint2  g_h1[NPAD * 32];   // half4: GEMM1 out (GAT1 gather input)
__device__ uint2  g_h2[NPAD * 32];   // half4: GAT1 out (GEMM2 A)
__device__ uint2  g_h3[NPAD * 32];   // half4: GEMM2 out (GAT2 gather input)
__device__ uint2  g_h4[MAXN * 32];   // half4: GAT2 out (mean-conv input)
__device__ __half g_W1h[DIM * DIM];
__device__ __half g_W2h[DIM * DIM];
__device__ float  g_val[768];        // v1s(2x128), v1d(2x128), u2s(128), u2d(128)
__device__ float g_as1[MAXN * 2];
__device__ float g_ad1[MAXN * 2];
__device__ float g_as2[MAXN];
__device__ float g_ad2[MAXN];
__device__ int g_rank[MAXE];
__device__ int g_csrc[MAXE];
__device__ int g_rowptr[MAXN + 1];
__device__ int g_cnt[MAXN];
__device__ int g_is64;

// ---------------- half4 <-> float4 ----------------
__device__ __forceinline__ float4 h4f4(uint2 u) {
    half2 a = *reinterpret_cast<half2*>(&u.x);
    half2 b = *reinterpret_cast<half2*>(&u.y);
    float2 fa = __half22float2(a), fb = __half22float2(b);
    float4 r; r.x = fa.x; r.y = fa.y; r.z = fb.x; r.w = fb.y; return r;
}
__device__ __forceinline__ uint2 f4h4(float4 v) {
    half2 a = __floats2half2_rn(v.x, v.y);
    half2 b = __floats2half2_rn(v.z, v.w);
    uint2 u;
    u.x = *reinterpret_cast<unsigned*>(&a);
    u.y = *reinterpret_cast<unsigned*>(&b);
    return u;
}
__device__ __forceinline__ float dot4(float4 a, float4 b) {
    return a.x * b.x + a.y * b.y + a.z * b.z + a.w * b.w;
}

// ---------------- dtype sniff ----------------
__global__ void detect_kernel(const unsigned int* __restrict__ raw, int E) {
    if (threadIdx.x != 0 || blockIdx.x != 0) return;
    int step = E / 64; if (step < 1) step = 1;
    int allz = 1;
    for (int k = 0; k < 64; k++) {
        long long j = 2LL * (long long)k * step + 1;
        if (j >= 2LL * E) break;
        if (raw[j] != 0u) { allz = 0; break; }
    }
    g_is64 = allz;
}

// ---------------- histogram + per-edge rank (reads raw dst only) ----------------
__global__ void convert_idx_kernel(const void* __restrict__ raw, int* __restrict__ rank,
                                   int* __restrict__ cnt, int E) {
    int i0 = (blockIdx.x * blockDim.x + threadIdx.x) * 4;
    if (i0 >= E) return;
    int m = min(4, E - i0);
    int dv[4];
    if (g_is64) {
        const int2* p = (const int2*)raw;
        #pragma unroll
        for (int k = 0; k < 4; k++) if (k < m) dv[k] = p[E + i0 + k].x;
    } else {
        const int* p = (const int*)raw;
        #pragma unroll
        for (int k = 0; k < 4; k++) if (k < m) dv[k] = p[E + i0 + k];
    }
    #pragma unroll
    for (int k = 0; k < 4; k++) if (k < m) rank[i0 + k] = atomicAdd(&cnt[dv[k]], 1);
}

// ---------------- single-block exclusive scan ----------------
__global__ void scan_kernel(const int* __restrict__ cnt, int* __restrict__ rowptr, int n) {
    __shared__ int part[1024];
    int t = threadIdx.x;
    int chunk = (n + 1023) >> 10;
    int b = t * chunk, e = min(b + chunk, n);
    int s = 0;
    for (int i = b; i < e; i++) s += cnt[i];
    part[t] = s;
    __syncthreads();
    #pragma unroll
    for (int off = 1; off < 1024; off <<= 1) {
        int v = (t >= off) ? part[t - off] : 0;
        __syncthreads();
        part[t] += v;
        __syncthreads();
    }
    int base = (t > 0) ? part[t - 1] : 0;
    for (int i = b; i < e; i++) { rowptr[i] = base; base += cnt[i]; }
    if (t == 1023) rowptr[n] = part[1023];
}

// ---------------- CSR fill: reads raw src/dst directly, pure scatter ----------------
__global__ void fill_kernel(const void* __restrict__ raw, const int* __restrict__ rank,
                            const int* __restrict__ rowptr, int* __restrict__ csrc, int E) {
    int i0 = (blockIdx.x * blockDim.x + threadIdx.x) * 4;
    if (i0 >= E) return;
    int m = min(4, E - i0);
    int sv[4], dv[4], rv[4], rp[4];
    if (g_is64) {
        const int2* p = (const int2*)raw;
        #pragma unroll
        for (int k = 0; k < 4; k++) if (k < m) { sv[k] = p[i0 + k].x; dv[k] = p[E + i0 + k].x; }
    } else {
        const int* p = (const int*)raw;
        #pragma unroll
        for (int k = 0; k < 4; k++) if (k < m) { sv[k] = p[i0 + k]; dv[k] = p[E + i0 + k]; }
    }
    #pragma unroll
    for (int k = 0; k < 4; k++) if (k < m) rv[k] = rank[i0 + k];
    #pragma unroll
    for (int k = 0; k < 4; k++) if (k < m) rp[k] = rowptr[dv[k]];
    #pragma unroll
    for (int k = 0; k < 4; k++) if (k < m) csrc[rp[k] + rv[k]] = sv[k];
}

// ---------------- prep: W -> fp16, fused logit vectors v = W^T a ----------------
__global__ void prep_kernel(const float* __restrict__ W1, const float* __restrict__ W2,
                            const float* __restrict__ a1s, const float* __restrict__ a1d,
                            const float* __restrict__ a2s, const float* __restrict__ a2d,
                            __half* __restrict__ W1h, __half* __restrict__ W2h,
                            float* __restrict__ val) {
    int t = threadIdx.x;
    for (int i = t; i < DIM * DIM; i += 256) {
        W1h[i] = __float2half(W1[i]);
        W2h[i] = __float2half(W2[i]);
    }
    if (t < 128) {
        int k = t;
        float s0 = 0.f, s1 = 0.f, d0 = 0.f, d1 = 0.f;
        for (int c = 0; c < 64; c++) {
            float w0 = W1[c * DIM + k], w1 = W1[(64 + c) * DIM + k];
            s0 += a1s[c] * w0;      s1 += a1s[64 + c] * w1;
            d0 += a1d[c] * w0;      d1 += a1d[64 + c] * w1;
        }
        val[k] = s0; val[128 + k] = s1; val[256 + k] = d0; val[384 + k] = d1;
        float us = 0.f, ud = 0.f;
        for (int o = 0; o < 128; o++) {
            float w = W2[o * DIM + k];
            us += a2s[o] * w; ud += a2d[o] * w;
        }
        val[512 + k] = us; val[640 + k] = ud;
    }
}

// ---------------- x -> fp16 + layer-1 logits (exact fp32 math) ----------------
__global__ void xconv_kernel(const float4* __restrict__ x, const float* __restrict__ val,
                             uint2* __restrict__ xh, float* __restrict__ as1,
                             float* __restrict__ ad1, int n) {
    int g = blockIdx.x * blockDim.x + threadIdx.x;
    int node = g >> 5, lane = g & 31;
    if (node >= n) return;
    float4 xv = x[node * 32 + lane];
    xh[node * 32 + lane] = f4h4(xv);
    float4 vs0 = ((const float4*)val)[lane];
    float4 vs1 = ((const float4*)(val + 128))[lane];
    float4 vd0 = ((const float4*)(val + 256))[lane];
    float4 vd1 = ((const float4*)(val + 384))[lane];
    float s0 = dot4(xv, vs0), s1 = dot4(xv, vs1);
    float d0 = dot4(xv, vd0), d1 = dot4(xv, vd1);
    #pragma unroll
    for (int off = 16; off >= 1; off >>= 1) {
        s0 += __shfl_xor_sync(0xffffffff, s0, off);
        s1 += __shfl_xor_sync(0xffffffff, s1, off);
        d0 += __shfl_xor_sync(0xffffffff, d0, off);
        d1 += __shfl_xor_sync(0xffffffff, d1, off);
    }
    if (lane == 0) {
        as1[node * 2] = s0; as1[node * 2 + 1] = s1;
        ad1[node * 2] = d0; ad1[node * 2 + 1] = d1;
    }
}

// ---------------- fp16 WMMA GEMM: C[m][o] = sum_k A[m][k] * W[o][k] ----------------
// Block tile 128x128, full K=128 in smem. 256 threads = 8 warps (4x2).
__global__ void hgemm_kernel(const __half* __restrict__ A, const __half* __restrict__ W,
                             __half* __restrict__ C, int nrows) {
    extern __shared__ __half smh[];
    __half* As = smh;              // [128][136]
    __half* Bs = smh + 128 * 136;  // [128][136]
    int tid = threadIdx.x;
    int row0 = blockIdx.x * 128;

    #pragma unroll
    for (int i = 0; i < 16; i++) {
        int idx = tid + i * 256;
        int r = idx >> 5, c4 = idx & 31;
        uint2 v = {0u, 0u};
        if (row0 + r < nrows) v = ((const uint2*)A)[(size_t)(row0 + r) * 32 + c4];
        *(uint2*)&As[r * 136 + c4 * 4] = v;
    }
    #pragma unroll
    for (int i = 0; i < 16; i++) {
        int idx = tid + i * 256;
        int r = idx >> 5, c4 = idx & 31;
        *(uint2*)&Bs[r * 136 + c4 * 4] = ((const uint2*)W)[idx];
    }
    __syncthreads();

    int wid = tid >> 5;
    int wm = wid >> 1, wn = wid & 1;   // wm: 4 row groups of 32; wn: 2 col groups of 64

    wmma::fragment<wmma::accumulator, 16, 16, 16, float> acc[2][4];
    #pragma unroll
    for (int i = 0; i < 2; i++)
        #pragma unroll
        for (int j = 0; j < 4; j++) wmma::fill_fragment(acc[i][j], 0.f);

    #pragma unroll
    for (int ks = 0; ks < 8; ks++) {
        wmma::fragment<wmma::matrix_a, 16, 16, 16, __half, wmma::row_major> af[2];
        #pragma unroll
        for (int i = 0; i < 2; i++)
            wmma::load_matrix_sync(af[i], &As[(wm * 32 + i * 16) * 136 + ks * 16], 136);
        wmma::fragment<wmma::matrix_b, 16, 16, 16, __half, wmma::col_major> bf[4];
        #pragma unroll
        for (int j = 0; j < 4; j++)
            wmma::load_matrix_sync(bf[j], &Bs[(wn * 64 + j * 16) * 136 + ks * 16], 136);
        #pragma unroll
        for (int i = 0; i < 2; i++)
            #pragma unroll
            for (int j = 0; j < 4; j++)
                wmma::mma_sync(acc[i][j], af[i], bf[j], acc[i][j]);
    }

    #pragma unroll
    for (int i = 0; i < 2; i++)
        #pragma unroll
        for (int j = 0; j < 4; j++) {
            wmma::fragment<wmma::accumulator, 16, 16, 16, __half> hf;
            #pragma unroll
            for (int e = 0; e < hf.num_elements; e++) hf.x[e] = __float2half(acc[i][j].x[e]);
            // row0 bounded by NPAD-padded scratch: unguarded store is in-bounds
            wmma::store_matrix_sync(&C[(size_t)(row0 + wm * 32 + i * 16) * DIM + wn * 64 + j * 16],
                                    hf, DIM, wmma::mem_row_major);
        }
}

// ---------------- GAT gather: warp/dst node, half in/out, x4 unroll ----------------
// ALPHA2: fuse layer-2 logit dots into epilogue (uses val[512..767])
template <int HEADS, bool RELU, bool ALPHA2>
__global__ void gat_gather_kernel(const int* __restrict__ rowptr, const int* __restrict__ csrc,
                                  const uint2* __restrict__ h, const float* __restrict__ as_,
                                  const float* __restrict__ ad_, const float* __restrict__ bias,
                                  const float* __restrict__ val, uint2* __restrict__ outh,
                                  float* __restrict__ as2, float* __restrict__ ad2, int n) {
    int g = blockIdx.x * blockDim.x + threadIdx.x;
    int d = g >> 5, lane = threadIdx.x & 31;
    if (d >= n) return;
    int head = (HEADS == 2) ? (lane >> 4) : 0;
    float adv = ad_[d * HEADS + head];

    float4 acc;
    float den;
    {   // self loop
        float a = as_[d * HEADS + head] + adv;
        float lr = (a > 0.f) ? a : 0.2f * a;
        float w = __expf(lr);
        float4 hv = h4f4(h[d * 32 + lane]);
        acc.x = w * hv.x; acc.y = w * hv.y; acc.z = w * hv.z; acc.w = w * hv.w;
        den = w;
    }

    int e0 = rowptr[d], e1 = rowptr[d + 1];
    int e = e0;
    for (; e + 4 <= e1; e += 4) {
        int s0 = csrc[e], s1 = csrc[e + 1], s2 = csrc[e + 2], s3 = csrc[e + 3];
        float a0 = as_[s0 * HEADS + head];
        float a1 = as_[s1 * HEADS + head];
        float a2 = as_[s2 * HEADS + head];
        float a3 = as_[s3 * HEADS + head];
        uint2 u0 = h[s0 * 32 + lane];
        uint2 u1 = h[s1 * 32 + lane];
        uint2 u2 = h[s2 * 32 + lane];
        uint2 u3 = h[s3 * 32 + lane];
        a0 += adv; a1 += adv; a2 += adv; a3 += adv;
        a0 = (a0 > 0.f) ? a0 : 0.2f * a0;
        a1 = (a1 > 0.f) ? a1 : 0.2f * a1;
        a2 = (a2 > 0.f) ? a2 : 0.2f * a2;
        a3 = (a3 > 0.f) ? a3 : 0.2f * a3;
        float w0 = __expf(a0), w1 = __expf(a1), w2 = __expf(a2), w3 = __expf(a3);
        float4 h0 = h4f4(u0), h1v = h4f4(u1), h2v = h4f4(u2), h3v = h4f4(u3);
        acc.x += w0 * h0.x + w1 * h1v.x + w2 * h2v.x + w3 * h3v.x;
        acc.y += w0 * h0.y + w1 * h1v.y + w2 * h2v.y + w3 * h3v.y;
        acc.z += w0 * h0.z + w1 * h1v.z + w2 * h2v.z + w3 * h3v.z;
        acc.w += w0 * h0.w + w1 * h1v.w + w2 * h2v.w + w3 * h3v.w;
        den += (w0 + w1) + (w2 + w3);
    }
    for (; e < e1; e++) {
        int s = csrc[e];
        float a = as_[s * HEADS + head] + adv;
        float lr = (a > 0.f) ? a : 0.2f * a;
        float w = __expf(lr);
        float4 hv = h4f4(h[s * 32 + lane]);
        acc.x += w * hv.x; acc.y += w * hv.y; acc.z += w * hv.z; acc.w += w * hv.w;
        den += w;
    }

    float inv = 1.f / den;
    float4 b = ((const float4*)bias)[lane];
    float4 r;
    r.x = acc.x * inv + b.x; r.y = acc.y * inv + b.y;
    r.z = acc.z * inv + b.z; r.w = acc.w * inv + b.w;
    if (RELU) {
        r.x = fmaxf(r.x, 0.f); r.y = fmaxf(r.y, 0.f);
        r.z = fmaxf(r.z, 0.f); r.w = fmaxf(r.w, 0.f);
    }
    outh[d * 32 + lane] = f4h4(r);

    if (ALPHA2) {
        float4 us = ((const float4*)(val + 512))[lane];
        float4 ud = ((const float4*)(val + 640))[lane];
        float ss = dot4(r, us), dd = dot4(r, ud);
        #pragma unroll
        for (int off = 16; off >= 1; off >>= 1) {
            ss += __shfl_xor_sync(0xffffffff, ss, off);
            dd += __shfl_xor_sync(0xffffffff, dd, off);
        }
        if (lane == 0) { as2[d] = ss; ad2[d] = dd; }
    }
}

// ---------------- mean conv gather (half in) + residual + relu ----------------
__global__ void mean_gather_kernel(const int* __restrict__ rowptr, const int* __restrict__ csrc,
                                   const uint2* __restrict__ h, const float4* __restrict__ x,
                                   float4* __restrict__ out, int n) {
    int g = blockIdx.x * blockDim.x + threadIdx.x;
    int d = g >> 5, lane = threadIdx.x & 31;
    if (d >= n) return;
    int e0 = rowptr[d], e1 = rowptr[d + 1];
    float4 acc = {0.f, 0.f, 0.f, 0.f};
    int e = e0;
    for (; e + 4 <= e1; e += 4) {
        int s0 = csrc[e], s1 = csrc[e + 1], s2 = csrc[e + 2], s3 = csrc[e + 3];
        float4 h0 = h4f4(h[s0 * 32 + lane]);
        float4 h1v = h4f4(h[s1 * 32 + lane]);
        float4 h2v = h4f4(h[s2 * 32 + lane]);
        float4 h3v = h4f4(h[s3 * 32 + lane]);
        acc.x += (h0.x + h1v.x) + (h2v.x + h3v.x);
        acc.y += (h0.y + h1v.y) + (h2v.y + h3v.y);
        acc.z += (h0.z + h1v.z) + (h2v.z + h3v.z);
        acc.w += (h0.w + h1v.w) + (h2v.w + h3v.w);
    }
    for (; e < e1; e++) {
        float4 hv = h4f4(h[csrc[e] * 32 + lane]);
        acc.x += hv.x; acc.y += hv.y; acc.z += hv.z; acc.w += hv.w;
    }
    int cnt = e1 - e0;
    float inv = (cnt > 0) ? (1.f / (float)cnt) : 0.f;
    float4 xv = x[d * 32 + lane];
    float4 r;
    r.x = fmaxf(acc.x * inv + xv.x, 0.f);
    r.y = fmaxf(acc.y * inv + xv.y, 0.f);
    r.z = fmaxf(acc.z * inv + xv.z, 0.f);
    r.w = fmaxf(acc.w * inv + xv.w, 0.f);
    out[d * 32 + lane] = r;
}

// ---------------- launch ----------------
extern "C" void kernel_launch(void* const* d_in, const int* in_sizes, int n_in,
                              void* d_out, int out_size) {
    const float* x    = (const float*)d_in[0];
    const void*  ei   = d_in[1];
    const float* W1   = (const float*)d_in[2];
    const float* asv1 = (const float*)d_in[3];
    const float* adv1 = (const float*)d_in[4];
    const float* b1   = (const float*)d_in[5];
    const float* W2   = (const float*)d_in[6];
    const float* asv2 = (const float*)d_in[7];
    const float* adv2 = (const float*)d_in[8];
    const float* b2   = (const float*)d_in[9];
    float* out = (float*)d_out;

    int n = in_sizes[0] / DIM;
    int E = in_sizes[1] / 2;

    uint2 *xh, *h1, *h2, *h3, *h4;
    __half *W1h, *W2h;
    float *val, *as1, *ad1, *as2, *ad2;
    int *rank, *csrc, *rowptr, *cnt;
    cudaGetSymbolAddress((void**)&xh,     g_xh);
    cudaGetSymbolAddress((void**)&h1,     g_h1);
    cudaGetSymbolAddress((void**)&h2,     g_h2);
    cudaGetSymbolAddress((void**)&h3,     g_h3);
    cudaGetSymbolAddress((void**)&h4,     g_h4);
    cudaGetSymbolAddress((void**)&W1h,    g_W1h);
    cudaGetSymbolAddress((void**)&W2h,    g_W2h);
    cudaGetSymbolAddress((void**)&val,    g_val);
    cudaGetSymbolAddress((void**)&as1,    g_as1);
    cudaGetSymbolAddress((void**)&ad1,    g_ad1);
    cudaGetSymbolAddress((void**)&as2,    g_as2);
    cudaGetSymbolAddress((void**)&ad2,    g_ad2);
    cudaGetSymbolAddress((void**)&rank,   g_rank);
    cudaGetSymbolAddress((void**)&csrc,   g_csrc);
    cudaGetSymbolAddress((void**)&rowptr, g_rowptr);
    cudaGetSymbolAddress((void**)&cnt,    g_cnt);

    const int hgemm_smem = 2 * 128 * 136 * (int)sizeof(__half);
    cudaFuncSetAttribute(hgemm_kernel, cudaFuncAttributeMaxDynamicSharedMemorySize, hgemm_smem);

    int gemm_blocks  = (n + 127) / 128;
    int nwarp_blocks = (n * 32 + 255) / 256;
    int e4_blocks    = ((E + 3) / 4 + 255) / 256;

    // ---- CSR build (by destination) ----
    detect_kernel<<<1, 32>>>((const unsigned int*)ei, E);
    cudaMemsetAsync(cnt, 0, (size_t)n * sizeof(int), 0);
    convert_idx_kernel<<<e4_blocks, 256>>>(ei, rank, cnt, E);
    scan_kernel<<<1, 1024>>>(cnt, rowptr, n);
    fill_kernel<<<e4_blocks, 256>>>(ei, rank, rowptr, csrc, E);

    // ---- prep + x conversion (layer-1 logits fused, exact fp32) ----
    prep_kernel<<<1, 256>>>(W1, W2, asv1, adv1, asv2, adv2, W1h, W2h, val);
    xconv_kernel<<<nwarp_blocks, 256>>>((const float4*)x, val, xh, as1, ad1, n);

    // ---- GAT layer 1 (heads=2, ch=64): WMMA GEMM + gather (alpha2 fused) ----
    hgemm_kernel<<<gemm_blocks, 256, hgemm_smem>>>((const __half*)xh, W1h, (__half*)h1, n);
    gat_gather_kernel<2, true, true><<<nwarp_blocks, 256>>>(rowptr, csrc, h1, as1, ad1, b1,
                                                            val, h2, as2, ad2, n);

    // ---- GAT layer 2 (heads=1, ch=128) ----
    hgemm_kernel<<<gemm_blocks, 256, hgemm_smem>>>((const __half*)h2, W2h, (__half*)h3, n);
    gat_gather_kernel<1, false, false><<<nwarp_blocks, 256>>>(rowptr, csrc, h3, as2, ad2, b2,
                                                              val, h4, nullptr, nullptr, n);

    // ---- mean conv + residual + relu ----
    mean_gather_kernel<<<nwarp_blocks, 256>>>(rowptr, csrc, h4, (const float4*)x,
                                              (float4*)out, n);
}

// round 7
// speedup vs baseline: 2.5372x; 1.1956x over previous
#include <cuda_runtime.h>
#include <cuda_fp16.h>
#include <mma.h>
using namespace nvcuda;

#define MAXN 50000
#define NPAD 50048          // padded rows so 128-row GEMM tiles store unguarded
#define MAXE 800000
#define DIM 128

// ---------------- scratch (allocation-free) ----------------
__device__ uint2  g_xh[NPAD * 32];   // half4: x in fp16 (GEMM1 A)
__device__ uint2  g_h1[NPAD * 32];   // half4: GEMM1 out (GAT1 gather input)
__device__ uint2  g_h2[NPAD * 32];   // half4: GAT1 out (GEMM2 A)
__device__ uint2  g_h3[NPAD * 32];   // half4: GEMM2 out (GAT2 gather input)
__device__ uint2  g_h4[MAXN * 32];   // half4: GAT2 out (mean-conv input)
__device__ __half g_W1h[DIM * DIM];
__device__ __half g_W2h[DIM * DIM];
__device__ float  g_val[768];        // v1s(2x128), v1d(2x128), u2s(128), u2d(128)
__device__ float g_as1[MAXN * 2];
__device__ float g_ad1[MAXN * 2];
__device__ float g_as2[MAXN];
__device__ float g_ad2[MAXN];
__device__ int g_rank[MAXE];
__device__ int g_csrc[MAXE];
__device__ int g_rowptr[MAXN + 1];
__device__ int g_cnt[MAXN];
__device__ int g_is64;

// ---------------- half4 <-> float4 ----------------
__device__ __forceinline__ float4 h4f4(uint2 u) {
    half2 a = *reinterpret_cast<half2*>(&u.x);
    half2 b = *reinterpret_cast<half2*>(&u.y);
    float2 fa = __half22float2(a), fb = __half22float2(b);
    float4 r; r.x = fa.x; r.y = fa.y; r.z = fb.x; r.w = fb.y; return r;
}
__device__ __forceinline__ uint2 f4h4(float4 v) {
    half2 a = __floats2half2_rn(v.x, v.y);
    half2 b = __floats2half2_rn(v.z, v.w);
    uint2 u;
    u.x = *reinterpret_cast<unsigned*>(&a);
    u.y = *reinterpret_cast<unsigned*>(&b);
    return u;
}
__device__ __forceinline__ float dot4(float4 a, float4 b) {
    return a.x * b.x + a.y * b.y + a.z * b.z + a.w * b.w;
}

// ---------------- dtype sniff ----------------
__global__ void detect_kernel(const unsigned int* __restrict__ raw, int E) {
    if (threadIdx.x != 0 || blockIdx.x != 0) return;
    int step = E / 64; if (step < 1) step = 1;
    int allz = 1;
    for (int k = 0; k < 64; k++) {
        long long j = 2LL * (long long)k * step + 1;
        if (j >= 2LL * E) break;
        if (raw[j] != 0u) { allz = 0; break; }
    }
    g_is64 = allz;
}

// ---------------- histogram + per-edge rank (8 edges/thread) ----------------
__global__ void convert_idx_kernel(const void* __restrict__ raw, int* __restrict__ rank,
                                   int* __restrict__ cnt, int E) {
    int i0 = (blockIdx.x * blockDim.x + threadIdx.x) * 8;
    if (i0 >= E) return;
    int m = min(8, E - i0);
    int dv[8];
    if (g_is64) {
        const int2* p = (const int2*)raw;
        #pragma unroll
        for (int k = 0; k < 8; k++) if (k < m) dv[k] = p[E + i0 + k].x;
    } else {
        const int* p = (const int*)raw;
        #pragma unroll
        for (int k = 0; k < 8; k++) if (k < m) dv[k] = p[E + i0 + k];
    }
    #pragma unroll
    for (int k = 0; k < 8; k++) if (k < m) rank[i0 + k] = atomicAdd(&cnt[dv[k]], 1);
}

// ---------------- single-block exclusive scan ----------------
__global__ void scan_kernel(const int* __restrict__ cnt, int* __restrict__ rowptr, int n) {
    __shared__ int part[1024];
    int t = threadIdx.x;
    int chunk = (n + 1023) >> 10;
    int b = t * chunk, e = min(b + chunk, n);
    int s = 0;
    for (int i = b; i < e; i++) s += cnt[i];
    part[t] = s;
    __syncthreads();
    #pragma unroll
    for (int off = 1; off < 1024; off <<= 1) {
        int v = (t >= off) ? part[t - off] : 0;
        __syncthreads();
        part[t] += v;
        __syncthreads();
    }
    int base = (t > 0) ? part[t - 1] : 0;
    for (int i = b; i < e; i++) { rowptr[i] = base; base += cnt[i]; }
    if (t == 1023) rowptr[n] = part[1023];
}

// ---------------- CSR fill: pure scatter, 8 edges/thread ----------------
__global__ void fill_kernel(const void* __restrict__ raw, const int* __restrict__ rank,
                            const int* __restrict__ rowptr, int* __restrict__ csrc, int E) {
    int i0 = (blockIdx.x * blockDim.x + threadIdx.x) * 8;
    if (i0 >= E) return;
    int m = min(8, E - i0);
    int sv[8], dv[8], rv[8], rp[8];
    if (g_is64) {
        const int2* p = (const int2*)raw;
        #pragma unroll
        for (int k = 0; k < 8; k++) if (k < m) { sv[k] = p[i0 + k].x; dv[k] = p[E + i0 + k].x; }
    } else {
        const int* p = (const int*)raw;
        #pragma unroll
        for (int k = 0; k < 8; k++) if (k < m) { sv[k] = p[i0 + k]; dv[k] = p[E + i0 + k]; }
    }
    #pragma unroll
    for (int k = 0; k < 8; k++) if (k < m) rv[k] = rank[i0 + k];
    #pragma unroll
    for (int k = 0; k < 8; k++) if (k < m) rp[k] = rowptr[dv[k]];
    #pragma unroll
    for (int k = 0; k < 8; k++) if (k < m) csrc[rp[k] + rv[k]] = sv[k];
}

// ---------------- prep: W -> fp16, fused logit vectors v = W^T a ----------------
__global__ void prep_kernel(const float* __restrict__ W1, const float* __restrict__ W2,
                            const float* __restrict__ a1s, const float* __restrict__ a1d,
                            const float* __restrict__ a2s, const float* __restrict__ a2d,
                            __half* __restrict__ W1h, __half* __restrict__ W2h,
                            float* __restrict__ val) {
    int t = threadIdx.x;
    for (int i = t; i < DIM * DIM; i += 256) {
        W1h[i] = __float2half(W1[i]);
        W2h[i] = __float2half(W2[i]);
    }
    if (t < 128) {
        int k = t;
        float s0 = 0.f, s1 = 0.f, d0 = 0.f, d1 = 0.f;
        for (int c = 0; c < 64; c++) {
            float w0 = W1[c * DIM + k], w1 = W1[(64 + c) * DIM + k];
            s0 += a1s[c] * w0;      s1 += a1s[64 + c] * w1;
            d0 += a1d[c] * w0;      d1 += a1d[64 + c] * w1;
        }
        val[k] = s0; val[128 + k] = s1; val[256 + k] = d0; val[384 + k] = d1;
        float us = 0.f, ud = 0.f;
        for (int o = 0; o < 128; o++) {
            float w = W2[o * DIM + k];
            us += a2s[o] * w; ud += a2d[o] * w;
        }
        val[512 + k] = us; val[640 + k] = ud;
    }
}

// ---------------- x -> fp16 + layer-1 logits (exact fp32 math) ----------------
__global__ void xconv_kernel(const float4* __restrict__ x, const float* __restrict__ val,
                             uint2* __restrict__ xh, float* __restrict__ as1,
                             float* __restrict__ ad1, int n) {
    int g = blockIdx.x * blockDim.x + threadIdx.x;
    int node = g >> 5, lane = g & 31;
    if (node >= n) return;
    float4 xv = x[node * 32 + lane];
    xh[node * 32 + lane] = f4h4(xv);
    float4 vs0 = ((const float4*)val)[lane];
    float4 vs1 = ((const float4*)(val + 128))[lane];
    float4 vd0 = ((const float4*)(val + 256))[lane];
    float4 vd1 = ((const float4*)(val + 384))[lane];
    float s0 = dot4(xv, vs0), s1 = dot4(xv, vs1);
    float d0 = dot4(xv, vd0), d1 = dot4(xv, vd1);
    #pragma unroll
    for (int off = 16; off >= 1; off >>= 1) {
        s0 += __shfl_xor_sync(0xffffffff, s0, off);
        s1 += __shfl_xor_sync(0xffffffff, s1, off);
        d0 += __shfl_xor_sync(0xffffffff, d0, off);
        d1 += __shfl_xor_sync(0xffffffff, d1, off);
    }
    if (lane == 0) {
        as1[node * 2] = s0; as1[node * 2 + 1] = s1;
        ad1[node * 2] = d0; ad1[node * 2 + 1] = d1;
    }
}

// ---------------- fp16 WMMA GEMM: C[m][o] = sum_k A[m][k] * W[o][k] ----------------
__global__ void hgemm_kernel(const __half* __restrict__ A, const __half* __restrict__ W,
                             __half* __restrict__ C, int nrows) {
    extern __shared__ __half smh[];
    __half* As = smh;              // [128][136]
    __half* Bs = smh + 128 * 136;  // [128][136]
    int tid = threadIdx.x;
    int row0 = blockIdx.x * 128;

    #pragma unroll
    for (int i = 0; i < 16; i++) {
        int idx = tid + i * 256;
        int r = idx >> 5, c4 = idx & 31;
        uint2 v = {0u, 0u};
        if (row0 + r < nrows) v = ((const uint2*)A)[(size_t)(row0 + r) * 32 + c4];
        *(uint2*)&As[r * 136 + c4 * 4] = v;
    }
    #pragma unroll
    for (int i = 0; i < 16; i++) {
        int idx = tid + i * 256;
        int r = idx >> 5, c4 = idx & 31;
        *(uint2*)&Bs[r * 136 + c4 * 4] = ((const uint2*)W)[idx];
    }
    __syncthreads();

    int wid = tid >> 5;
    int wm = wid >> 1, wn = wid & 1;

    wmma::fragment<wmma::accumulator, 16, 16, 16, float> acc[2][4];
    #pragma unroll
    for (int i = 0; i < 2; i++)
        #pragma unroll
        for (int j = 0; j < 4; j++) wmma::fill_fragment(acc[i][j], 0.f);

    #pragma unroll
    for (int ks = 0; ks < 8; ks++) {
        wmma::fragment<wmma::matrix_a, 16, 16, 16, __half, wmma::row_major> af[2];
        #pragma unroll
        for (int i = 0; i < 2; i++)
            wmma::load_matrix_sync(af[i], &As[(wm * 32 + i * 16) * 136 + ks * 16], 136);
        wmma::fragment<wmma::matrix_b, 16, 16, 16, __half, wmma::col_major> bf[4];
        #pragma unroll
        for (int j = 0; j < 4; j++)
            wmma::load_matrix_sync(bf[j], &Bs[(wn * 64 + j * 16) * 136 + ks * 16], 136);
        #pragma unroll
        for (int i = 0; i < 2; i++)
            #pragma unroll
            for (int j = 0; j < 4; j++)
                wmma::mma_sync(acc[i][j], af[i], bf[j], acc[i][j]);
    }

    #pragma unroll
    for (int i = 0; i < 2; i++)
        #pragma unroll
        for (int j = 0; j < 4; j++) {
            wmma::fragment<wmma::accumulator, 16, 16, 16, __half> hf;
            #pragma unroll
            for (int e = 0; e < hf.num_elements; e++) hf.x[e] = __float2half(acc[i][j].x[e]);
            wmma::store_matrix_sync(&C[(size_t)(row0 + wm * 32 + i * 16) * DIM + wn * 64 + j * 16],
                                    hf, DIM, wmma::mem_row_major);
        }
}

// ---------------- GAT gather: warp/dst node, x8 batched loads for MLP ----------------
template <int HEADS, bool RELU, bool ALPHA2>
__global__ void __launch_bounds__(256)
gat_gather_kernel(const int* __restrict__ rowptr, const int* __restrict__ csrc,
                  const uint2* __restrict__ h, const float* __restrict__ as_,
                  const float* __restrict__ ad_, const float* __restrict__ bias,
                  const float* __restrict__ val, uint2* __restrict__ outh,
                  float* __restrict__ as2, float* __restrict__ ad2, int n) {
    int g = blockIdx.x * blockDim.x + threadIdx.x;
    int d = g >> 5, lane = threadIdx.x & 31;
    if (d >= n) return;
    int head = (HEADS == 2) ? (lane >> 4) : 0;
    float adv = ad_[d * HEADS + head];

    float4 acc;
    float den;
    {   // self loop
        float a = as_[d * HEADS + head] + adv;
        float lr = (a > 0.f) ? a : 0.2f * a;
        float w = __expf(lr);
        float4 hv = h4f4(h[d * 32 + lane]);
        acc.x = w * hv.x; acc.y = w * hv.y; acc.z = w * hv.z; acc.w = w * hv.w;
        den = w;
    }

    int e0 = rowptr[d], e1 = rowptr[d + 1];
    int e = e0;
    for (; e + 8 <= e1; e += 8) {
        int s[8];
        #pragma unroll
        for (int k = 0; k < 8; k++) s[k] = csrc[e + k];
        float a[8];
        #pragma unroll
        for (int k = 0; k < 8; k++) a[k] = as_[s[k] * HEADS + head];
        uint2 u[8];
        #pragma unroll
        for (int k = 0; k < 8; k++) u[k] = h[s[k] * 32 + lane];
        #pragma unroll
        for (int k = 0; k < 8; k++) {
            float t = a[k] + adv;
            t = (t > 0.f) ? t : 0.2f * t;
            float w = __expf(t);
            float4 hv = h4f4(u[k]);
            acc.x += w * hv.x; acc.y += w * hv.y;
            acc.z += w * hv.z; acc.w += w * hv.w;
            den += w;
        }
    }
    for (; e < e1; e++) {
        int s = csrc[e];
        float a = as_[s * HEADS + head] + adv;
        float lr = (a > 0.f) ? a : 0.2f * a;
        float w = __expf(lr);
        float4 hv = h4f4(h[s * 32 + lane]);
        acc.x += w * hv.x; acc.y += w * hv.y; acc.z += w * hv.z; acc.w += w * hv.w;
        den += w;
    }

    float inv = 1.f / den;
    float4 b = ((const float4*)bias)[lane];
    float4 r;
    r.x = acc.x * inv + b.x; r.y = acc.y * inv + b.y;
    r.z = acc.z * inv + b.z; r.w = acc.w * inv + b.w;
    if (RELU) {
        r.x = fmaxf(r.x, 0.f); r.y = fmaxf(r.y, 0.f);
        r.z = fmaxf(r.z, 0.f); r.w = fmaxf(r.w, 0.f);
    }
    outh[d * 32 + lane] = f4h4(r);

    if (ALPHA2) {
        float4 us = ((const float4*)(val + 512))[lane];
        float4 ud = ((const float4*)(val + 640))[lane];
        float ss = dot4(r, us), dd = dot4(r, ud);
        #pragma unroll
        for (int off = 16; off >= 1; off >>= 1) {
            ss += __shfl_xor_sync(0xffffffff, ss, off);
            dd += __shfl_xor_sync(0xffffffff, dd, off);
        }
        if (lane == 0) { as2[d] = ss; ad2[d] = dd; }
    }
}

// ---------------- mean conv gather (half in) + residual + relu (x8) ----------------
__global__ void __launch_bounds__(256)
mean_gather_kernel(const int* __restrict__ rowptr, const int* __restrict__ csrc,
                   const uint2* __restrict__ h, const float4* __restrict__ x,
                   float4* __restrict__ out, int n) {
    int g = blockIdx.x * blockDim.x + threadIdx.x;
    int d = g >> 5, lane = threadIdx.x & 31;
    if (d >= n) return;
    int e0 = rowptr[d], e1 = rowptr[d + 1];
    float4 acc = {0.f, 0.f, 0.f, 0.f};
    int e = e0;
    for (; e + 8 <= e1; e += 8) {
        int s[8];
        #pragma unroll
        for (int k = 0; k < 8; k++) s[k] = csrc[e + k];
        uint2 u[8];
        #pragma unroll
        for (int k = 0; k < 8; k++) u[k] = h[s[k] * 32 + lane];
        #pragma unroll
        for (int k = 0; k < 8; k++) {
            float4 hv = h4f4(u[k]);
            acc.x += hv.x; acc.y += hv.y; acc.z += hv.z; acc.w += hv.w;
        }
    }
    for (; e < e1; e++) {
        float4 hv = h4f4(h[csrc[e] * 32 + lane]);
        acc.x += hv.x; acc.y += hv.y; acc.z += hv.z; acc.w += hv.w;
    }
    int cnt = e1 - e0;
    float inv = (cnt > 0) ? (1.f / (float)cnt) : 0.f;
    float4 xv = x[d * 32 + lane];
    float4 r;
    r.x = fmaxf(acc.x * inv + xv.x, 0.f);
    r.y = fmaxf(acc.y * inv + xv.y, 0.f);
    r.z = fmaxf(acc.z * inv + xv.z, 0.f);
    r.w = fmaxf(acc.w * inv + xv.w, 0.f);
    out[d * 32 + lane] = r;
}

// ---------------- launch ----------------
extern "C" void kernel_launch(void* const* d_in, const int* in_sizes, int n_in,
                              void* d_out, int out_size) {
    const float* x    = (const float*)d_in[0];
    const void*  ei   = d_in[1];
    const float* W1   = (const float*)d_in[2];
    const float* asv1 = (const float*)d_in[3];
    const float* adv1 = (const float*)d_in[4];
    const float* b1   = (const float*)d_in[5];
    const float* W2   = (const float*)d_in[6];
    const float* asv2 = (const float*)d_in[7];
    const float* adv2 = (const float*)d_in[8];
    const float* b2   = (const float*)d_in[9];
    float* out = (float*)d_out;

    int n = in_sizes[0] / DIM;
    int E = in_sizes[1] / 2;

    uint2 *xh, *h1, *h2, *h3, *h4;
    __half *W1h, *W2h;
    float *val, *as1, *ad1, *as2, *ad2;
    int *rank, *csrc, *rowptr, *cnt;
    cudaGetSymbolAddress((void**)&xh,     g_xh);
    cudaGetSymbolAddress((void**)&h1,     g_h1);
    cudaGetSymbolAddress((void**)&h2,     g_h2);
    cudaGetSymbolAddress((void**)&h3,     g_h3);
    cudaGetSymbolAddress((void**)&h4,     g_h4);
    cudaGetSymbolAddress((void**)&W1h,    g_W1h);
    cudaGetSymbolAddress((void**)&W2h,    g_W2h);
    cudaGetSymbolAddress((void**)&val,    g_val);
    cudaGetSymbolAddress((void**)&as1,    g_as1);
    cudaGetSymbolAddress((void**)&ad1,    g_ad1);
    cudaGetSymbolAddress((void**)&as2,    g_as2);
    cudaGetSymbolAddress((void**)&ad2,    g_ad2);
    cudaGetSymbolAddress((void**)&rank,   g_rank);
    cudaGetSymbolAddress((void**)&csrc,   g_csrc);
    cudaGetSymbolAddress((void**)&rowptr, g_rowptr);
    cudaGetSymbolAddress((void**)&cnt,    g_cnt);

    const int hgemm_smem = 2 * 128 * 136 * (int)sizeof(__half);
    cudaFuncSetAttribute(hgemm_kernel, cudaFuncAttributeMaxDynamicSharedMemorySize, hgemm_smem);

    int gemm_blocks  = (n + 127) / 128;
    int nwarp_blocks = (n * 32 + 255) / 256;
    int e8_blocks    = ((E + 7) / 8 + 255) / 256;

    // ---- fork: CSR build on side stream, feature prep on main stream ----
    cudaStream_t s;
    cudaStreamCreateWithFlags(&s, cudaStreamNonBlocking);
    cudaEvent_t evFork, evJoin;
    cudaEventCreateWithFlags(&evFork, cudaEventDisableTiming);
    cudaEventCreateWithFlags(&evJoin, cudaEventDisableTiming);

    cudaEventRecord(evFork, 0);
    cudaStreamWaitEvent(s, evFork, 0);

    // side stream: CSR build (by destination)
    detect_kernel<<<1, 32, 0, s>>>((const unsigned int*)ei, E);
    cudaMemsetAsync(cnt, 0, (size_t)n * sizeof(int), s);
    convert_idx_kernel<<<e8_blocks, 256, 0, s>>>(ei, rank, cnt, E);
    scan_kernel<<<1, 1024, 0, s>>>(cnt, rowptr, n);
    fill_kernel<<<e8_blocks, 256, 0, s>>>(ei, rank, rowptr, csrc, E);
    cudaEventRecord(evJoin, s);

    // main stream: prep + x conversion + GEMM1 (no CSR dependency)
    prep_kernel<<<1, 256>>>(W1, W2, asv1, adv1, asv2, adv2, W1h, W2h, val);
    xconv_kernel<<<nwarp_blocks, 256>>>((const float4*)x, val, xh, as1, ad1, n);
    hgemm_kernel<<<gemm_blocks, 256, hgemm_smem>>>((const __half*)xh, W1h, (__half*)h1, n);

    // join: gather-1 needs both CSR and h1
    cudaStreamWaitEvent(0, evJoin, 0);

    gat_gather_kernel<2, true, true><<<nwarp_blocks, 256>>>(rowptr, csrc, h1, as1, ad1, b1,
                                                            val, h2, as2, ad2, n);

    hgemm_kernel<<<gemm_blocks, 256, hgemm_smem>>>((const __half*)h2, W2h, (__half*)h3, n);
    gat_gather_kernel<1, false, false><<<nwarp_blocks, 256>>>(rowptr, csrc, h3, as2, ad2, b2,
                                                              val, h4, nullptr, nullptr, n);

    mean_gather_kernel<<<nwarp_blocks, 256>>>(rowptr, csrc, h4, (const float4*)x,
                                              (float4*)out, n);
    // note: stream/events intentionally not destroyed during potential capture
}